// round 10
// baseline (speedup 1.0000x reference)
#include <cuda_runtime.h>
#include <stdint.h>
#include <math.h>

#define BZ 8
#define LQ 1024
#define D  512
#define NH 8
#define DH 64

// ---------------- scratch ----------------
__device__ float g_h[BZ * LQ * D];            // fp32 h (exact, for fixup + residual)
__device__ uint32_t g_ht[BZ * LQ * D];        // tf32 bits of h
__device__ uint32_t g_Wt[3 * D * D];          // tf32 bits of Wq,Wk,Wv
__device__ float g_Q[BZ * LQ * D];            // tf32 bits, pre-scaled by 1/8
__device__ float g_K[BZ * LQ * D];            // tf32 bits
__device__ float g_V[BZ * LQ * D];            // tf32 bits
__device__ float g_norm[BZ * LQ];
__device__ unsigned long long g_mbits[(size_t)BZ * LQ * (LQ / 64)];  // bit=1: masked

// ---------------- helpers ----------------
__device__ __forceinline__ uint32_t f2tf(float f) {
    uint32_t u;
    asm("cvt.rna.tf32.f32 %0, %1;" : "=r"(u) : "f"(f));
    return u;
}
__device__ __forceinline__ void mma8(float* d, const uint32_t* a, const uint32_t* b) {
    asm volatile(
        "mma.sync.aligned.m16n8k8.row.col.f32.tf32.tf32.f32 "
        "{%0,%1,%2,%3},{%4,%5,%6,%7},{%8,%9},{%0,%1,%2,%3};\n"
        : "+f"(d[0]), "+f"(d[1]), "+f"(d[2]), "+f"(d[3])
        : "r"(a[0]), "r"(a[1]), "r"(a[2]), "r"(a[3]), "r"(b[0]), "r"(b[1]));
}
__device__ __forceinline__ void cpasync16(uint32_t saddr, const void* g) {
    asm volatile("cp.async.cg.shared.global [%0], [%1], 16;" :: "r"(saddr), "l"(g));
}
#define CP_COMMIT() asm volatile("cp.async.commit_group;")
#define CP_WAIT0()  asm volatile("cp.async.wait_group 0;")
#define CP_WAIT1()  asm volatile("cp.async.wait_group 1;")

#define KP 20
#define PANEL (128 * KP)          // uint32 per stage per matrix

// ---------------- K1: transpose + row norms + tf32 copy ----------------
__global__ __launch_bounds__(128) void k_prep(const float* __restrict__ q) {
    int row = blockIdx.x;              // r = i*BZ + b
    int i = row >> 3, b = row & 7;
    int tid = threadIdx.x, lane = tid & 31, wid = tid >> 5;
    float4 v = ((const float4*)(q + (size_t)row * D))[tid];
    size_t di = (size_t)(b * LQ + i) * (D / 4) + tid;
    ((float4*)g_h)[di] = v;
    uint4 u;
    u.x = f2tf(v.x); u.y = f2tf(v.y); u.z = f2tf(v.z); u.w = f2tf(v.w);
    ((uint4*)g_ht)[di] = u;
    float s = v.x * v.x + v.y * v.y + v.z * v.z + v.w * v.w;
    #pragma unroll
    for (int o = 16; o; o >>= 1) s += __shfl_xor_sync(0xffffffffu, s, o);
    __shared__ float ws[4];
    if (lane == 0) ws[wid] = s;
    __syncthreads();
    if (tid == 0)
        g_norm[b * LQ + i] = fmaxf(sqrtf(ws[0] + ws[1] + ws[2] + ws[3]), 1e-8f);
}

// ---------------- K1b: convert weights to tf32 bits ----------------
__global__ __launch_bounds__(256) void k_cvtw(
    const float* __restrict__ W0, const float* __restrict__ W1, const float* __restrict__ W2) {
    int idx = blockIdx.x * 256 + threadIdx.x;    // float4 units; 65536 per matrix
    int z = idx >> 16, r = idx & 65535;
    const float* W = (z == 0) ? W0 : (z == 1) ? W1 : W2;
    float4 v = ((const float4*)W)[r];
    uint4 u;
    u.x = f2tf(v.x); u.y = f2tf(v.y); u.z = f2tf(v.z); u.w = f2tf(v.w);
    ((uint4*)g_Wt)[z * 65536 + r] = u;
}

// ---------------- K2: fused QKV GEMM, 3-stage cp.async pipeline ----------------
__global__ __launch_bounds__(256, 2) void k_gemm_qkv(
    const float* __restrict__ b0, const float* __restrict__ b1, const float* __restrict__ b2,
    float* __restrict__ C0, float* __restrict__ C1, float* __restrict__ C2)
{
    const int N = D, K = D;
    int z = blockIdx.z;
    const float* bias = (z == 0) ? b0 : (z == 1) ? b1 : b2;
    float*       C    = (z == 0) ? C0 : (z == 1) ? C1 : C2;
    float oscale = (z == 0) ? 0.125f : 1.0f;
    const uint32_t* Wsel = g_Wt + (size_t)z * D * D;

    extern __shared__ __align__(16) uint32_t dsm[];
    uint32_t* As = dsm;                    // [3][128][KP]
    uint32_t* Bs = dsm + 3 * PANEL;        // [3][128][KP]

    int tid = threadIdx.x, lane = tid & 31, wid = tid >> 5;
    int g = lane >> 2, q = lane & 3;
    int wm = wid >> 2, wn = wid & 3;
    int m0 = blockIdx.y * 128, n0 = blockIdx.x * 128;

    int lrow = tid >> 1, lc = (tid & 1) * 8;
    const uint32_t* Ap = g_ht + (size_t)(m0 + lrow) * K + lc;
    const uint32_t* Bp = Wsel + (size_t)(n0 + lrow) * K + lc;
    uint32_t sA = (uint32_t)__cvta_generic_to_shared(As + lrow * KP + lc);
    uint32_t sB = (uint32_t)__cvta_generic_to_shared(Bs + lrow * KP + lc);

    const int nP = K / 16;    // 32 panels
    #pragma unroll
    for (int s = 0; s < 2; s++) {         // prologue: panels 0,1
        cpasync16(sA + s * PANEL * 4,      Ap + s * 16);
        cpasync16(sA + s * PANEL * 4 + 16, Ap + s * 16 + 4);
        cpasync16(sB + s * PANEL * 4,      Bp + s * 16);
        cpasync16(sB + s * PANEL * 4 + 16, Bp + s * 16 + 4);
        CP_COMMIT();
    }

    float acc[4][4][4] = {};
    for (int p = 0; p < nP; p++) {
        if (p + 1 < nP) CP_WAIT1(); else CP_WAIT0();
        __syncthreads();
        if (p + 2 < nP) {
            int st = (p + 2) % 3;
            cpasync16(sA + st * PANEL * 4,      Ap + (p + 2) * 16);
            cpasync16(sA + st * PANEL * 4 + 16, Ap + (p + 2) * 16 + 4);
            cpasync16(sB + st * PANEL * 4,      Bp + (p + 2) * 16);
            cpasync16(sB + st * PANEL * 4 + 16, Bp + (p + 2) * 16 + 4);
            CP_COMMIT();
        }
        const uint32_t* Ab = As + (p % 3) * PANEL;
        const uint32_t* Bb = Bs + (p % 3) * PANEL;
        #pragma unroll
        for (int ks = 0; ks < 2; ks++) {
            int k8 = ks * 8;
            uint32_t af[4][4], bf[4][2];
            #pragma unroll
            for (int mt = 0; mt < 4; mt++) {
                int mb = wm * 64 + mt * 16;
                af[mt][0] = Ab[(mb + g) * KP + k8 + q];
                af[mt][1] = Ab[(mb + g + 8) * KP + k8 + q];
                af[mt][2] = Ab[(mb + g) * KP + k8 + q + 4];
                af[mt][3] = Ab[(mb + g + 8) * KP + k8 + q + 4];
            }
            #pragma unroll
            for (int nt = 0; nt < 4; nt++) {
                int nb2 = wn * 32 + nt * 8 + g;
                bf[nt][0] = Bb[nb2 * KP + k8 + q];
                bf[nt][1] = Bb[nb2 * KP + k8 + q + 4];
            }
            #pragma unroll
            for (int mt = 0; mt < 4; mt++)
                #pragma unroll
                for (int nt = 0; nt < 4; nt++) mma8(acc[mt][nt], af[mt], bf[nt]);
        }
    }

    #pragma unroll
    for (int mt = 0; mt < 4; mt++)
        #pragma unroll
        for (int h2 = 0; h2 < 2; h2++) {
            int m = m0 + wm * 64 + mt * 16 + g + h2 * 8;
            #pragma unroll
            for (int nt = 0; nt < 4; nt++) {
                int n = n0 + wn * 32 + nt * 8 + 2 * q;
                float2 v;
                v.x = __uint_as_float(f2tf((acc[mt][nt][h2 * 2 + 0] + bias[n]) * oscale));
                v.y = __uint_as_float(f2tf((acc[mt][nt][h2 * 2 + 1] + bias[n + 1]) * oscale));
                *(float2*)&C[(size_t)m * N + n] = v;
            }
        }
}

// ---------------- K3: mask -> bitpacked words, 3-stage pipeline ----------------
__global__ __launch_bounds__(256, 2) void k_mask(const float* __restrict__ seg) {
    extern __shared__ __align__(16) uint32_t dsm[];
    uint32_t* As = dsm;                    // [3][128][KP]
    uint32_t* Bs = dsm + 3 * PANEL;
    __shared__ float si[128], ei[128], li[128], ni[128];
    __shared__ float sj[128], ej[128], lj[128], nj[128];

    int b = blockIdx.z;
    int t = blockIdx.x;
    int it = 0;
    while ((it + 1) * (it + 2) / 2 <= t) it++;
    int jt = t - it * (it + 1) / 2;
    int i0 = it * 128, j0 = jt * 128;

    int tid = threadIdx.x, lane = tid & 31, wid = tid >> 5;
    int g = lane >> 2, q = lane & 3;
    int wm = wid >> 2, wn = wid & 3;

    if (tid < 128) {
        int gi = b * LQ + i0 + tid;
        float c = seg[gi * 2], l = seg[gi * 2 + 1];
        si[tid] = c - 0.5f * l; ei[tid] = c + 0.5f * l; li[tid] = l;
        ni[tid] = g_norm[gi];
    } else {
        int tt = tid - 128;
        int gj = b * LQ + j0 + tt;
        float c = seg[gj * 2], l = seg[gj * 2 + 1];
        sj[tt] = c - 0.5f * l; ej[tt] = c + 0.5f * l; lj[tt] = l;
        nj[tt] = g_norm[gj];
    }

    const uint32_t* Tbase = g_ht + (size_t)b * LQ * D;
    const float*    Abase = g_h  + (size_t)b * LQ * D;
    int lrow = tid >> 1, lc = (tid & 1) * 8;
    const uint32_t* Ap = Tbase + (size_t)(i0 + lrow) * D + lc;
    const uint32_t* Bp = Tbase + (size_t)(j0 + lrow) * D + lc;
    uint32_t sA = (uint32_t)__cvta_generic_to_shared(As + lrow * KP + lc);
    uint32_t sB = (uint32_t)__cvta_generic_to_shared(Bs + lrow * KP + lc);

    const int nP = D / 16;
    #pragma unroll
    for (int s = 0; s < 2; s++) {
        cpasync16(sA + s * PANEL * 4,      Ap + s * 16);
        cpasync16(sA + s * PANEL * 4 + 16, Ap + s * 16 + 4);
        cpasync16(sB + s * PANEL * 4,      Bp + s * 16);
        cpasync16(sB + s * PANEL * 4 + 16, Bp + s * 16 + 4);
        CP_COMMIT();
    }

    float acc[4][4][4] = {};
    for (int p = 0; p < nP; p++) {
        if (p + 1 < nP) CP_WAIT1(); else CP_WAIT0();
        __syncthreads();
        if (p + 2 < nP) {
            int st = (p + 2) % 3;
            cpasync16(sA + st * PANEL * 4,      Ap + (p + 2) * 16);
            cpasync16(sA + st * PANEL * 4 + 16, Ap + (p + 2) * 16 + 4);
            cpasync16(sB + st * PANEL * 4,      Bp + (p + 2) * 16);
            cpasync16(sB + st * PANEL * 4 + 16, Bp + (p + 2) * 16 + 4);
            CP_COMMIT();
        }
        const uint32_t* Ab = As + (p % 3) * PANEL;
        const uint32_t* Bb = Bs + (p % 3) * PANEL;
        #pragma unroll
        for (int ks = 0; ks < 2; ks++) {
            int k8 = ks * 8;
            uint32_t af[4][4], bf[4][2];
            #pragma unroll
            for (int mt = 0; mt < 4; mt++) {
                int mb = wm * 64 + mt * 16;
                af[mt][0] = Ab[(mb + g) * KP + k8 + q];
                af[mt][1] = Ab[(mb + g + 8) * KP + k8 + q];
                af[mt][2] = Ab[(mb + g) * KP + k8 + q + 4];
                af[mt][3] = Ab[(mb + g + 8) * KP + k8 + q + 4];
            }
            #pragma unroll
            for (int nt = 0; nt < 4; nt++) {
                int nb2 = wn * 32 + nt * 8 + g;
                bf[nt][0] = Bb[nb2 * KP + k8 + q];
                bf[nt][1] = Bb[nb2 * KP + k8 + q + 4];
            }
            #pragma unroll
            for (int mt = 0; mt < 4; mt++)
                #pragma unroll
                for (int nt = 0; nt < 4; nt++) mma8(acc[mt][nt], af[mt], bf[nt]);
        }
    }
    __syncthreads();    // mainloop + all cp.async done; reuse dsm as byte staging

    unsigned char* Ms = (unsigned char*)dsm;            // [128][132]
    unsigned char* Ts = Ms + 128 * 132;                 // [128][132]

    #pragma unroll
    for (int mt = 0; mt < 4; mt++)
        #pragma unroll
        for (int h2 = 0; h2 < 2; h2++) {
            int ii = wm * 64 + mt * 16 + g + h2 * 8;
            int gi = i0 + ii;
            #pragma unroll
            for (int nt = 0; nt < 4; nt++) {
                int jc = wn * 32 + nt * 8 + 2 * q;
                #pragma unroll
                for (int e = 0; e < 2; e++) {
                    int jj = jc + e, gj = j0 + jj;
                    float inv_nn = 1.f / (ni[ii] * nj[jj]);
                    float cosv = acc[mt][nt][h2 * 2 + e] * inv_nn;
                    if (fabsf(cosv - 0.2f) < 2e-3f) {
                        const float4* ra = (const float4*)(Abase + (size_t)gi * D);
                        const float4* rb = (const float4*)(Abase + (size_t)gj * D);
                        float dot = 0.f;
                        #pragma unroll 4
                        for (int k = 0; k < D / 4; k++) {
                            float4 x = ra[k], y = rb[k];
                            dot += x.x * y.x + x.y * y.y + x.z * y.z + x.w * y.w;
                        }
                        cosv = dot * inv_nn;
                    }
                    float inter = fmaxf(fminf(ei[ii], ej[jj]) - fmaxf(si[ii], sj[jj]), 0.f);
                    float uni   = li[ii] + lj[jj] - inter;
                    float iou   = inter / uni;
                    bool masked = (cosv <= 0.2f) || (iou > 0.2f && gi != gj);
                    unsigned char mb = masked ? 1 : 0;
                    Ms[ii * 132 + jj] = mb;
                    Ts[jj * 132 + ii] = mb;
                }
            }
        }
    __syncthreads();

    {
        int row = tid >> 1, grp = tid & 1;
        const unsigned char* src = Ms + row * 132 + grp * 64;
        unsigned long long bits = 0ull;
        #pragma unroll 16
        for (int c = 0; c < 64; c++) bits |= (unsigned long long)src[c] << c;
        g_mbits[((size_t)b * LQ + i0 + row) * 16 + jt * 2 + grp] = bits;
        if (it != jt) {
            src = Ts + row * 132 + grp * 64;
            bits = 0ull;
            #pragma unroll 16
            for (int c = 0; c < 64; c++) bits |= (unsigned long long)src[c] << c;
            g_mbits[((size_t)b * LQ + j0 + row) * 16 + it * 2 + grp] = bits;
        }
    }
}

// ---------------- K4: FA2 flash attention, bitmask-driven tile skipping ----------------
#define ATP 68
#define KVTILE (64 * ATP)
__global__ __launch_bounds__(256, 2) void k_attn(float* __restrict__ out) {
    extern __shared__ float sm[];
    uint32_t* Qs = (uint32_t*)sm;          // 128*ATP, persistent
    uint32_t* KV = Qs + 128 * ATP;         // single buffer: K tile + V tile

    int i0 = blockIdx.x * 128, head = blockIdx.y, b = blockIdx.z;
    int tid = threadIdx.x, lane = tid & 31, wid = tid >> 5;
    int g = lane >> 2, q = lane & 3;
    const size_t base = (size_t)b * LQ * D + head * DH;

    #pragma unroll
    for (int s = 0; s < 8; s++) {
        int f = tid + s * 256;
        int r = f >> 4, c4 = (f & 15) << 2;
        cpasync16((uint32_t)__cvta_generic_to_shared(Qs + r * ATP + c4),
                  &g_Q[base + (size_t)(i0 + r) * D + c4]);
    }
    CP_COMMIT();

    int lr = wid * 16;
    int gi0 = i0 + lr;
    float O[8][4] = {};
    float m0 = -1e30f, m1 = -1e30f, l0 = 0.f, l1 = 0.f;

    const unsigned long long* mb0 = g_mbits + ((size_t)b * LQ + gi0 + g) * 16;
    const unsigned long long* mb1 = g_mbits + ((size_t)b * LQ + gi0 + g + 8) * 16;

    for (int j = 0; j < 16; j++) {
        unsigned long long w0 = mb0[j], w1 = mb1[j];
        int any_un = ((w0 & w1) != 0xFFFFFFFFFFFFFFFFull);
        int blk_active = __syncthreads_or(any_un);
        if (!blk_active) continue;

        int j0 = j * 64;
        #pragma unroll
        for (int s = 0; s < 4; s++) {
            int f = tid + s * 256;
            int r = f >> 4, c4 = (f & 15) << 2;
            size_t ga = base + (size_t)(j0 + r) * D + c4;
            cpasync16((uint32_t)__cvta_generic_to_shared(KV + r * ATP + c4), &g_K[ga]);
            cpasync16((uint32_t)__cvta_generic_to_shared(KV + KVTILE + r * ATP + c4), &g_V[ga]);
        }
        CP_COMMIT();
        CP_WAIT0();
        __syncthreads();

        unsigned wact = __ballot_sync(0xffffffffu, any_un);
        if (!wact) continue;

        const uint32_t* Ks = KV;
        const uint32_t* Vs = KV + KVTILE;

        float S[8][4] = {};
        #pragma unroll
        for (int ks = 0; ks < 8; ks++) {
            uint32_t af[4];
            af[0] = Qs[(lr + g) * ATP + ks * 8 + q];
            af[1] = Qs[(lr + g + 8) * ATP + ks * 8 + q];
            af[2] = Qs[(lr + g) * ATP + ks * 8 + q + 4];
            af[3] = Qs[(lr + g + 8) * ATP + ks * 8 + q + 4];
            uint32_t bf[8][2];
            #pragma unroll
            for (int nt = 0; nt < 8; nt++) {
                bf[nt][0] = Ks[(nt * 8 + g) * ATP + ks * 8 + q];
                bf[nt][1] = Ks[(nt * 8 + g) * ATP + ks * 8 + q + 4];
            }
            #pragma unroll
            for (int nt = 0; nt < 8; nt++) mma8(S[nt], af, bf[nt]);
        }

        #pragma unroll
        for (int nt = 0; nt < 8; nt++) {
            int c = nt * 8 + 2 * q;
            if ((w0 >> c) & 1)       S[nt][0] = -1e30f;
            if ((w0 >> (c + 1)) & 1) S[nt][1] = -1e30f;
            if ((w1 >> c) & 1)       S[nt][2] = -1e30f;
            if ((w1 >> (c + 1)) & 1) S[nt][3] = -1e30f;
        }

        float mx0 = -1e30f, mx1 = -1e30f;
        #pragma unroll
        for (int nt = 0; nt < 8; nt++) {
            mx0 = fmaxf(mx0, fmaxf(S[nt][0], S[nt][1]));
            mx1 = fmaxf(mx1, fmaxf(S[nt][2], S[nt][3]));
        }
        #pragma unroll
        for (int o = 1; o < 4; o <<= 1) {
            mx0 = fmaxf(mx0, __shfl_xor_sync(0xffffffffu, mx0, o));
            mx1 = fmaxf(mx1, __shfl_xor_sync(0xffffffffu, mx1, o));
        }
        float mn0 = fmaxf(m0, mx0), mn1 = fmaxf(m1, mx1);

        uint32_t (*P)[4] = (uint32_t(*)[4])S;
        float s0 = 0.f, s1 = 0.f;
        #pragma unroll
        for (int nt = 0; nt < 8; nt++) {
            float p00 = __expf(S[nt][0] - mn0), p01 = __expf(S[nt][1] - mn0);
            float p10 = __expf(S[nt][2] - mn1), p11 = __expf(S[nt][3] - mn1);
            s0 += p00 + p01; s1 += p10 + p11;
            P[nt][0] = f2tf(p00); P[nt][1] = f2tf(p01);
            P[nt][2] = f2tf(p10); P[nt][3] = f2tf(p11);
        }
        #pragma unroll
        for (int o = 1; o < 4; o <<= 1) {
            s0 += __shfl_xor_sync(0xffffffffu, s0, o);
            s1 += __shfl_xor_sync(0xffffffffu, s1, o);
        }
        float sc0 = __expf(m0 - mn0), sc1 = __expf(m1 - mn1);
        l0 = l0 * sc0 + s0; l1 = l1 * sc1 + s1;
        m0 = mn0; m1 = mn1;

        #pragma unroll
        for (int nt = 0; nt < 8; nt++) {
            O[nt][0] *= sc0; O[nt][1] *= sc0;
            O[nt][2] *= sc1; O[nt][3] *= sc1;
        }

        #pragma unroll
        for (int kc = 0; kc < 8; kc++) {
            uint32_t af[4] = {P[kc][0], P[kc][2], P[kc][1], P[kc][3]};
            uint32_t bf[8][2];
            #pragma unroll
            for (int nt = 0; nt < 8; nt++) {
                bf[nt][0] = Vs[(kc * 8 + 2 * q) * ATP + nt * 8 + g];
                bf[nt][1] = Vs[(kc * 8 + 2 * q + 1) * ATP + nt * 8 + g];
            }
            #pragma unroll
            for (int nt = 0; nt < 8; nt++) mma8(O[nt], af, bf[nt]);
        }
    }

    float inv0 = 1.f / l0, inv1 = 1.f / l1;
    int r0 = gi0 + g, r1 = gi0 + g + 8;
    #pragma unroll
    for (int nt = 0; nt < 8; nt++) {
        int col = head * DH + nt * 8 + 2 * q;
        float2 h0 = *(const float2*)&g_h[((size_t)b * LQ + r0) * D + col];
        float2 h1 = *(const float2*)&g_h[((size_t)b * LQ + r1) * D + col];
        float2 o0, o1;
        o0.x = O[nt][0] * inv0 + h0.x; o0.y = O[nt][1] * inv0 + h0.y;
        o1.x = O[nt][2] * inv1 + h1.x; o1.y = O[nt][3] * inv1 + h1.y;
        *(float2*)&out[((size_t)r0 * BZ + b) * D + col] = o0;
        *(float2*)&out[((size_t)r1 * BZ + b) * D + col] = o1;
    }
}

// ---------------- host ----------------
extern "C" void kernel_launch(void* const* d_in, const int* in_sizes, int n_in,
                              void* d_out, int out_size) {
    const float* query = (const float*)d_in[0];
    const float* seg   = (const float*)d_in[1];
    const float* Wq    = (const float*)d_in[2];
    const float* bq    = (const float*)d_in[3];
    const float* Wk    = (const float*)d_in[4];
    const float* bk    = (const float*)d_in[5];
    const float* Wv    = (const float*)d_in[6];
    const float* bv    = (const float*)d_in[7];
    float* out = (float*)d_out;

    float *qp, *kp, *vp;
    cudaGetSymbolAddress((void**)&qp, g_Q);
    cudaGetSymbolAddress((void**)&kp, g_K);
    cudaGetSymbolAddress((void**)&vp, g_V);

    k_prep<<<BZ * LQ, 128>>>(query);
    k_cvtw<<<3 * 65536 / 256, 256>>>(Wq, Wk, Wv);

    int smem_g = 6 * PANEL * (int)sizeof(uint32_t);   // 61440 B
    cudaFuncSetAttribute(k_gemm_qkv, cudaFuncAttributeMaxDynamicSharedMemorySize, smem_g);
    cudaFuncSetAttribute(k_mask,     cudaFuncAttributeMaxDynamicSharedMemorySize, smem_g);

    dim3 gg(D / 128, BZ * LQ / 128, 3);   // (4, 64, 3)
    k_gemm_qkv<<<gg, 256, smem_g>>>(bq, bk, bv, qp, kp, vp);

    dim3 gm(36, 1, BZ);                   // lower-triangle tile pairs
    k_mask<<<gm, 256, smem_g>>>(seg);

    int smem_a = (128 * ATP + 2 * KVTILE) * (int)sizeof(float);   // 69632 B
    cudaFuncSetAttribute(k_attn, cudaFuncAttributeMaxDynamicSharedMemorySize, smem_a);
    dim3 ga(LQ / 128, NH, BZ);            // (8, 8, 8)
    k_attn<<<ga, 256, smem_a>>>(out);
}

// round 11
// speedup vs baseline: 1.1162x; 1.1162x over previous
#include <cuda_runtime.h>
#include <stdint.h>
#include <math.h>

#define BZ 8
#define LQ 1024
#define D  512
#define NH 8
#define DH 64

// ---------------- scratch ----------------
__device__ float g_h[BZ * LQ * D];            // fp32 h (exact, for fixup + residual)
__device__ uint32_t g_ht[BZ * LQ * D];        // tf32 bits of h
__device__ uint32_t g_Wt[3 * D * D];          // tf32 bits of Wq,Wk,Wv
__device__ float g_Q[BZ * LQ * D];            // tf32 bits, pre-scaled by 1/8
__device__ float g_K[BZ * LQ * D];            // tf32 bits
__device__ float g_V[BZ * LQ * D];            // tf32 bits
__device__ float g_norm[BZ * LQ];
__device__ unsigned long long g_mbits[(size_t)BZ * LQ * (LQ / 64)];  // bit=1: masked

// ---------------- helpers ----------------
__device__ __forceinline__ uint32_t f2tf(float f) {
    uint32_t u;
    asm("cvt.rna.tf32.f32 %0, %1;" : "=r"(u) : "f"(f));
    return u;
}
__device__ __forceinline__ void mma8(float* d, const uint32_t* a, const uint32_t* b) {
    asm volatile(
        "mma.sync.aligned.m16n8k8.row.col.f32.tf32.tf32.f32 "
        "{%0,%1,%2,%3},{%4,%5,%6,%7},{%8,%9},{%0,%1,%2,%3};\n"
        : "+f"(d[0]), "+f"(d[1]), "+f"(d[2]), "+f"(d[3])
        : "r"(a[0]), "r"(a[1]), "r"(a[2]), "r"(a[3]), "r"(b[0]), "r"(b[1]));
}
__device__ __forceinline__ void cpasync16(uint32_t saddr, const void* g) {
    asm volatile("cp.async.cg.shared.global [%0], [%1], 16;" :: "r"(saddr), "l"(g));
}
#define CP_COMMIT() asm volatile("cp.async.commit_group;")
#define CP_WAIT0()  asm volatile("cp.async.wait_group 0;")
#define CP_WAIT1()  asm volatile("cp.async.wait_group 1;")

#define KP 20
#define PANEL (128 * KP)          // uint32 per stage per matrix
#define GEMM_BLOCKS (4 * 64 * 3)  // 768
#define MASK_BLOCKS (36)          // per batch

// ---------------- K1: prep (transpose + norms + tf32) fused with weight cvt ----------------
__global__ __launch_bounds__(128) void k_prep(
    const float* __restrict__ q,
    const float* __restrict__ W0, const float* __restrict__ W1, const float* __restrict__ W2) {
    if (blockIdx.x < BZ * LQ) {
        int row = blockIdx.x;              // r = i*BZ + b
        int i = row >> 3, b = row & 7;
        int tid = threadIdx.x, lane = tid & 31, wid = tid >> 5;
        float4 v = ((const float4*)(q + (size_t)row * D))[tid];
        size_t di = (size_t)(b * LQ + i) * (D / 4) + tid;
        ((float4*)g_h)[di] = v;
        uint4 u;
        u.x = f2tf(v.x); u.y = f2tf(v.y); u.z = f2tf(v.z); u.w = f2tf(v.w);
        ((uint4*)g_ht)[di] = u;
        float s = v.x * v.x + v.y * v.y + v.z * v.z + v.w * v.w;
        #pragma unroll
        for (int o = 16; o; o >>= 1) s += __shfl_xor_sync(0xffffffffu, s, o);
        __shared__ float ws[4];
        if (lane == 0) ws[wid] = s;
        __syncthreads();
        if (tid == 0)
            g_norm[b * LQ + i] = fmaxf(sqrtf(ws[0] + ws[1] + ws[2] + ws[3]), 1e-8f);
    } else {
        int idx = (blockIdx.x - BZ * LQ) * 128 + threadIdx.x;  // float4 units
        int z = idx >> 16, r = idx & 65535;
        const float* W = (z == 0) ? W0 : (z == 1) ? W1 : W2;
        float4 v = ((const float4*)W)[r];
        uint4 u;
        u.x = f2tf(v.x); u.y = f2tf(v.y); u.z = f2tf(v.z); u.w = f2tf(v.w);
        ((uint4*)g_Wt)[z * 65536 + r] = u;
    }
}

// ---------------- K2: FUSED  [QKV GEMM blocks | mask Gram blocks] ----------------
__global__ __launch_bounds__(256, 2) void k_gemm_mask(
    const float* __restrict__ seg,
    const float* __restrict__ b0, const float* __restrict__ b1, const float* __restrict__ b2,
    float* __restrict__ C0, float* __restrict__ C1, float* __restrict__ C2)
{
    extern __shared__ __align__(16) uint32_t dsm[];
    uint32_t* As = dsm;                    // [3][128][KP]
    uint32_t* Bs = dsm + 3 * PANEL;

    int tid = threadIdx.x, lane = tid & 31, wid = tid >> 5;
    int g = lane >> 2, q = lane & 3;
    int wm = wid >> 2, wn = wid & 3;
    int lrow = tid >> 1, lc = (tid & 1) * 8;
    uint32_t sA = (uint32_t)__cvta_generic_to_shared(As + lrow * KP + lc);
    uint32_t sB = (uint32_t)__cvta_generic_to_shared(Bs + lrow * KP + lc);

    if (blockIdx.x < GEMM_BLOCKS) {
        // ---------- QKV GEMM path ----------
        const int N = D, K = D;
        int idx = blockIdx.x;
        int z = idx >> 8;                 // 256 blocks per matrix
        int r = idx & 255;
        int n0 = (r & 3) * 128, m0 = (r >> 2) * 128;
        const float* bias = (z == 0) ? b0 : (z == 1) ? b1 : b2;
        float*       C    = (z == 0) ? C0 : (z == 1) ? C1 : C2;
        float oscale = (z == 0) ? 0.125f : 1.0f;

        const uint32_t* Ap = g_ht + (size_t)(m0 + lrow) * K + lc;
        const uint32_t* Bp = g_Wt + (size_t)z * D * D + (size_t)(n0 + lrow) * K + lc;

        const int nP = K / 16;
        #pragma unroll
        for (int s = 0; s < 2; s++) {
            cpasync16(sA + s * PANEL * 4,      Ap + s * 16);
            cpasync16(sA + s * PANEL * 4 + 16, Ap + s * 16 + 4);
            cpasync16(sB + s * PANEL * 4,      Bp + s * 16);
            cpasync16(sB + s * PANEL * 4 + 16, Bp + s * 16 + 4);
            CP_COMMIT();
        }

        float acc[4][4][4] = {};
        for (int p = 0; p < nP; p++) {
            if (p + 1 < nP) CP_WAIT1(); else CP_WAIT0();
            __syncthreads();
            if (p + 2 < nP) {
                int st = (p + 2) % 3;
                cpasync16(sA + st * PANEL * 4,      Ap + (p + 2) * 16);
                cpasync16(sA + st * PANEL * 4 + 16, Ap + (p + 2) * 16 + 4);
                cpasync16(sB + st * PANEL * 4,      Bp + (p + 2) * 16);
                cpasync16(sB + st * PANEL * 4 + 16, Bp + (p + 2) * 16 + 4);
                CP_COMMIT();
            }
            const uint32_t* Ab = As + (p % 3) * PANEL;
            const uint32_t* Bb = Bs + (p % 3) * PANEL;
            #pragma unroll
            for (int ks = 0; ks < 2; ks++) {
                int k8 = ks * 8;
                uint32_t af[4][4], bf[4][2];
                #pragma unroll
                for (int mt = 0; mt < 4; mt++) {
                    int mb = wm * 64 + mt * 16;
                    af[mt][0] = Ab[(mb + g) * KP + k8 + q];
                    af[mt][1] = Ab[(mb + g + 8) * KP + k8 + q];
                    af[mt][2] = Ab[(mb + g) * KP + k8 + q + 4];
                    af[mt][3] = Ab[(mb + g + 8) * KP + k8 + q + 4];
                }
                #pragma unroll
                for (int nt = 0; nt < 4; nt++) {
                    int nb2 = wn * 32 + nt * 8 + g;
                    bf[nt][0] = Bb[nb2 * KP + k8 + q];
                    bf[nt][1] = Bb[nb2 * KP + k8 + q + 4];
                }
                #pragma unroll
                for (int mt = 0; mt < 4; mt++)
                    #pragma unroll
                    for (int nt = 0; nt < 4; nt++) mma8(acc[mt][nt], af[mt], bf[nt]);
            }
        }

        #pragma unroll
        for (int mt = 0; mt < 4; mt++)
            #pragma unroll
            for (int h2 = 0; h2 < 2; h2++) {
                int m = m0 + wm * 64 + mt * 16 + g + h2 * 8;
                #pragma unroll
                for (int nt = 0; nt < 4; nt++) {
                    int n = n0 + wn * 32 + nt * 8 + 2 * q;
                    float2 v;
                    v.x = __uint_as_float(f2tf((acc[mt][nt][h2 * 2 + 0] + bias[n]) * oscale));
                    v.y = __uint_as_float(f2tf((acc[mt][nt][h2 * 2 + 1] + bias[n + 1]) * oscale));
                    *(float2*)&C[(size_t)m * N + n] = v;
                }
            }
    } else {
        // ---------- mask Gram path ----------
        __shared__ float si[128], ei[128], li[128], ni[128];
        __shared__ float sj[128], ej[128], lj[128], nj[128];
        int t = blockIdx.x - GEMM_BLOCKS;
        int b = t / MASK_BLOCKS;
        t -= b * MASK_BLOCKS;
        int it = 0;
        while ((it + 1) * (it + 2) / 2 <= t) it++;
        int jt = t - it * (it + 1) / 2;
        int i0 = it * 128, j0 = jt * 128;

        if (tid < 128) {
            int gi = b * LQ + i0 + tid;
            float c = seg[gi * 2], l = seg[gi * 2 + 1];
            si[tid] = c - 0.5f * l; ei[tid] = c + 0.5f * l; li[tid] = l;
            ni[tid] = g_norm[gi];
        } else {
            int tt = tid - 128;
            int gj = b * LQ + j0 + tt;
            float c = seg[gj * 2], l = seg[gj * 2 + 1];
            sj[tt] = c - 0.5f * l; ej[tt] = c + 0.5f * l; lj[tt] = l;
            nj[tt] = g_norm[gj];
        }

        const uint32_t* Tbase = g_ht + (size_t)b * LQ * D;
        const float*    Abase = g_h  + (size_t)b * LQ * D;
        const uint32_t* Ap = Tbase + (size_t)(i0 + lrow) * D + lc;
        const uint32_t* Bp = Tbase + (size_t)(j0 + lrow) * D + lc;

        const int nP = D / 16;
        #pragma unroll
        for (int s = 0; s < 2; s++) {
            cpasync16(sA + s * PANEL * 4,      Ap + s * 16);
            cpasync16(sA + s * PANEL * 4 + 16, Ap + s * 16 + 4);
            cpasync16(sB + s * PANEL * 4,      Bp + s * 16);
            cpasync16(sB + s * PANEL * 4 + 16, Bp + s * 16 + 4);
            CP_COMMIT();
        }

        float acc[4][4][4] = {};
        for (int p = 0; p < nP; p++) {
            if (p + 1 < nP) CP_WAIT1(); else CP_WAIT0();
            __syncthreads();
            if (p + 2 < nP) {
                int st = (p + 2) % 3;
                cpasync16(sA + st * PANEL * 4,      Ap + (p + 2) * 16);
                cpasync16(sA + st * PANEL * 4 + 16, Ap + (p + 2) * 16 + 4);
                cpasync16(sB + st * PANEL * 4,      Bp + (p + 2) * 16);
                cpasync16(sB + st * PANEL * 4 + 16, Bp + (p + 2) * 16 + 4);
                CP_COMMIT();
            }
            const uint32_t* Ab = As + (p % 3) * PANEL;
            const uint32_t* Bb = Bs + (p % 3) * PANEL;
            #pragma unroll
            for (int ks = 0; ks < 2; ks++) {
                int k8 = ks * 8;
                uint32_t af[4][4], bf[4][2];
                #pragma unroll
                for (int mt = 0; mt < 4; mt++) {
                    int mb = wm * 64 + mt * 16;
                    af[mt][0] = Ab[(mb + g) * KP + k8 + q];
                    af[mt][1] = Ab[(mb + g + 8) * KP + k8 + q];
                    af[mt][2] = Ab[(mb + g) * KP + k8 + q + 4];
                    af[mt][3] = Ab[(mb + g + 8) * KP + k8 + q + 4];
                }
                #pragma unroll
                for (int nt = 0; nt < 4; nt++) {
                    int nb2 = wn * 32 + nt * 8 + g;
                    bf[nt][0] = Bb[nb2 * KP + k8 + q];
                    bf[nt][1] = Bb[nb2 * KP + k8 + q + 4];
                }
                #pragma unroll
                for (int mt = 0; mt < 4; mt++)
                    #pragma unroll
                    for (int nt = 0; nt < 4; nt++) mma8(acc[mt][nt], af[mt], bf[nt]);
            }
        }
        __syncthreads();    // mainloop + all cp.async done; reuse dsm as byte staging

        unsigned char* Ms = (unsigned char*)dsm;            // [128][132]
        unsigned char* Ts = Ms + 128 * 132;                 // [128][132]

        #pragma unroll
        for (int mt = 0; mt < 4; mt++)
            #pragma unroll
            for (int h2 = 0; h2 < 2; h2++) {
                int ii = wm * 64 + mt * 16 + g + h2 * 8;
                int gi = i0 + ii;
                #pragma unroll
                for (int nt = 0; nt < 4; nt++) {
                    int jc = wn * 32 + nt * 8 + 2 * q;
                    #pragma unroll
                    for (int e = 0; e < 2; e++) {
                        int jj = jc + e, gj = j0 + jj;
                        float inv_nn = 1.f / (ni[ii] * nj[jj]);
                        float cosv = acc[mt][nt][h2 * 2 + e] * inv_nn;
                        if (fabsf(cosv - 0.2f) < 2e-3f) {
                            const float4* ra = (const float4*)(Abase + (size_t)gi * D);
                            const float4* rb = (const float4*)(Abase + (size_t)gj * D);
                            float dot = 0.f;
                            #pragma unroll 4
                            for (int k = 0; k < D / 4; k++) {
                                float4 x = ra[k], y = rb[k];
                                dot += x.x * y.x + x.y * y.y + x.z * y.z + x.w * y.w;
                            }
                            cosv = dot * inv_nn;
                        }
                        float inter = fmaxf(fminf(ei[ii], ej[jj]) - fmaxf(si[ii], sj[jj]), 0.f);
                        float uni   = li[ii] + lj[jj] - inter;
                        float iou   = inter / uni;
                        bool masked = (cosv <= 0.2f) || (iou > 0.2f && gi != gj);
                        unsigned char mb = masked ? 1 : 0;
                        Ms[ii * 132 + jj] = mb;
                        Ts[jj * 132 + ii] = mb;
                    }
                }
            }
        __syncthreads();

        {
            int row = tid >> 1, grp = tid & 1;
            const unsigned char* src = Ms + row * 132 + grp * 64;
            unsigned long long bits = 0ull;
            #pragma unroll 16
            for (int c = 0; c < 64; c++) bits |= (unsigned long long)src[c] << c;
            g_mbits[((size_t)b * LQ + i0 + row) * 16 + jt * 2 + grp] = bits;
            if (it != jt) {
                src = Ts + row * 132 + grp * 64;
                bits = 0ull;
                #pragma unroll 16
                for (int c = 0; c < 64; c++) bits |= (unsigned long long)src[c] << c;
                g_mbits[((size_t)b * LQ + j0 + row) * 16 + it * 2 + grp] = bits;
            }
        }
    }
}

// ---------------- K3: FA2 flash attention, bitmask-driven tile skipping ----------------
#define ATP 68
#define KVTILE (64 * ATP)
__global__ __launch_bounds__(256, 2) void k_attn(float* __restrict__ out) {
    extern __shared__ float sm[];
    uint32_t* Qs = (uint32_t*)sm;          // 128*ATP, persistent
    uint32_t* KV = Qs + 128 * ATP;         // single buffer: K tile + V tile

    int i0 = blockIdx.x * 128, head = blockIdx.y, b = blockIdx.z;
    int tid = threadIdx.x, lane = tid & 31, wid = tid >> 5;
    int g = lane >> 2, q = lane & 3;
    const size_t base = (size_t)b * LQ * D + head * DH;

    #pragma unroll
    for (int s = 0; s < 8; s++) {
        int f = tid + s * 256;
        int r = f >> 4, c4 = (f & 15) << 2;
        cpasync16((uint32_t)__cvta_generic_to_shared(Qs + r * ATP + c4),
                  &g_Q[base + (size_t)(i0 + r) * D + c4]);
    }
    CP_COMMIT();

    int lr = wid * 16;
    int gi0 = i0 + lr;
    float O[8][4] = {};
    float m0 = -1e30f, m1 = -1e30f, l0 = 0.f, l1 = 0.f;

    const unsigned long long* mb0 = g_mbits + ((size_t)b * LQ + gi0 + g) * 16;
    const unsigned long long* mb1 = g_mbits + ((size_t)b * LQ + gi0 + g + 8) * 16;

    for (int j = 0; j < 16; j++) {
        unsigned long long w0 = mb0[j], w1 = mb1[j];
        int any_un = ((w0 & w1) != 0xFFFFFFFFFFFFFFFFull);
        int blk_active = __syncthreads_or(any_un);
        if (!blk_active) continue;

        int j0 = j * 64;
        #pragma unroll
        for (int s = 0; s < 4; s++) {
            int f = tid + s * 256;
            int r = f >> 4, c4 = (f & 15) << 2;
            size_t ga = base + (size_t)(j0 + r) * D + c4;
            cpasync16((uint32_t)__cvta_generic_to_shared(KV + r * ATP + c4), &g_K[ga]);
            cpasync16((uint32_t)__cvta_generic_to_shared(KV + KVTILE + r * ATP + c4), &g_V[ga]);
        }
        CP_COMMIT();
        CP_WAIT0();
        __syncthreads();

        unsigned wact = __ballot_sync(0xffffffffu, any_un);
        if (!wact) continue;

        const uint32_t* Ks = KV;
        const uint32_t* Vs = KV + KVTILE;

        float S[8][4] = {};
        #pragma unroll
        for (int ks = 0; ks < 8; ks++) {
            uint32_t af[4];
            af[0] = Qs[(lr + g) * ATP + ks * 8 + q];
            af[1] = Qs[(lr + g + 8) * ATP + ks * 8 + q];
            af[2] = Qs[(lr + g) * ATP + ks * 8 + q + 4];
            af[3] = Qs[(lr + g + 8) * ATP + ks * 8 + q + 4];
            uint32_t bf[8][2];
            #pragma unroll
            for (int nt = 0; nt < 8; nt++) {
                bf[nt][0] = Ks[(nt * 8 + g) * ATP + ks * 8 + q];
                bf[nt][1] = Ks[(nt * 8 + g) * ATP + ks * 8 + q + 4];
            }
            #pragma unroll
            for (int nt = 0; nt < 8; nt++) mma8(S[nt], af, bf[nt]);
        }

        #pragma unroll
        for (int nt = 0; nt < 8; nt++) {
            int c = nt * 8 + 2 * q;
            if ((w0 >> c) & 1)       S[nt][0] = -1e30f;
            if ((w0 >> (c + 1)) & 1) S[nt][1] = -1e30f;
            if ((w1 >> c) & 1)       S[nt][2] = -1e30f;
            if ((w1 >> (c + 1)) & 1) S[nt][3] = -1e30f;
        }

        float mx0 = -1e30f, mx1 = -1e30f;
        #pragma unroll
        for (int nt = 0; nt < 8; nt++) {
            mx0 = fmaxf(mx0, fmaxf(S[nt][0], S[nt][1]));
            mx1 = fmaxf(mx1, fmaxf(S[nt][2], S[nt][3]));
        }
        #pragma unroll
        for (int o = 1; o < 4; o <<= 1) {
            mx0 = fmaxf(mx0, __shfl_xor_sync(0xffffffffu, mx0, o));
            mx1 = fmaxf(mx1, __shfl_xor_sync(0xffffffffu, mx1, o));
        }
        float mn0 = fmaxf(m0, mx0), mn1 = fmaxf(m1, mx1);

        uint32_t (*P)[4] = (uint32_t(*)[4])S;
        float s0 = 0.f, s1 = 0.f;
        #pragma unroll
        for (int nt = 0; nt < 8; nt++) {
            float p00 = __expf(S[nt][0] - mn0), p01 = __expf(S[nt][1] - mn0);
            float p10 = __expf(S[nt][2] - mn1), p11 = __expf(S[nt][3] - mn1);
            s0 += p00 + p01; s1 += p10 + p11;
            P[nt][0] = f2tf(p00); P[nt][1] = f2tf(p01);
            P[nt][2] = f2tf(p10); P[nt][3] = f2tf(p11);
        }
        #pragma unroll
        for (int o = 1; o < 4; o <<= 1) {
            s0 += __shfl_xor_sync(0xffffffffu, s0, o);
            s1 += __shfl_xor_sync(0xffffffffu, s1, o);
        }
        float sc0 = __expf(m0 - mn0), sc1 = __expf(m1 - mn1);
        l0 = l0 * sc0 + s0; l1 = l1 * sc1 + s1;
        m0 = mn0; m1 = mn1;

        #pragma unroll
        for (int nt = 0; nt < 8; nt++) {
            O[nt][0] *= sc0; O[nt][1] *= sc0;
            O[nt][2] *= sc1; O[nt][3] *= sc1;
        }

        #pragma unroll
        for (int kc = 0; kc < 8; kc++) {
            uint32_t af[4] = {P[kc][0], P[kc][2], P[kc][1], P[kc][3]};
            uint32_t bf[8][2];
            #pragma unroll
            for (int nt = 0; nt < 8; nt++) {
                bf[nt][0] = Vs[(kc * 8 + 2 * q) * ATP + nt * 8 + g];
                bf[nt][1] = Vs[(kc * 8 + 2 * q + 1) * ATP + nt * 8 + g];
            }
            #pragma unroll
            for (int nt = 0; nt < 8; nt++) mma8(O[nt], af, bf[nt]);
        }
    }

    float inv0 = 1.f / l0, inv1 = 1.f / l1;
    int r0 = gi0 + g, r1 = gi0 + g + 8;
    #pragma unroll
    for (int nt = 0; nt < 8; nt++) {
        int col = head * DH + nt * 8 + 2 * q;
        float2 h0 = *(const float2*)&g_h[((size_t)b * LQ + r0) * D + col];
        float2 h1 = *(const float2*)&g_h[((size_t)b * LQ + r1) * D + col];
        float2 o0, o1;
        o0.x = O[nt][0] * inv0 + h0.x; o0.y = O[nt][1] * inv0 + h0.y;
        o1.x = O[nt][2] * inv1 + h1.x; o1.y = O[nt][3] * inv1 + h1.y;
        *(float2*)&out[((size_t)r0 * BZ + b) * D + col] = o0;
        *(float2*)&out[((size_t)r1 * BZ + b) * D + col] = o1;
    }
}

// ---------------- host ----------------
extern "C" void kernel_launch(void* const* d_in, const int* in_sizes, int n_in,
                              void* d_out, int out_size) {
    const float* query = (const float*)d_in[0];
    const float* seg   = (const float*)d_in[1];
    const float* Wq    = (const float*)d_in[2];
    const float* bq    = (const float*)d_in[3];
    const float* Wk    = (const float*)d_in[4];
    const float* bk    = (const float*)d_in[5];
    const float* Wv    = (const float*)d_in[6];
    const float* bv    = (const float*)d_in[7];
    float* out = (float*)d_out;

    float *qp, *kp, *vp;
    cudaGetSymbolAddress((void**)&qp, g_Q);
    cudaGetSymbolAddress((void**)&kp, g_K);
    cudaGetSymbolAddress((void**)&vp, g_V);

    // prep (8192 blocks) + weight cvt (1536 blocks), fused
    k_prep<<<BZ * LQ + 3 * 65536 / 128, 128>>>(query, Wq, Wk, Wv);

    int smem_g = 6 * PANEL * (int)sizeof(uint32_t);   // 61440 B
    cudaFuncSetAttribute(k_gemm_mask, cudaFuncAttributeMaxDynamicSharedMemorySize, smem_g);
    // fused: 768 GEMM blocks + 288 mask blocks, co-scheduled
    k_gemm_mask<<<GEMM_BLOCKS + MASK_BLOCKS * BZ, 256, smem_g>>>(
        seg, bq, bk, bv, qp, kp, vp);

    int smem_a = (128 * ATP + 2 * KVTILE) * (int)sizeof(float);   // 69632 B
    cudaFuncSetAttribute(k_attn, cudaFuncAttributeMaxDynamicSharedMemorySize, smem_a);
    dim3 ga(LQ / 128, NH, BZ);            // (8, 8, 8)
    k_attn<<<ga, 256, smem_a>>>(out);
}

// round 12
// speedup vs baseline: 1.5683x; 1.4050x over previous
#include <cuda_runtime.h>
#include <cuda_fp16.h>
#include <stdint.h>
#include <math.h>

#define BZ 8
#define LQ 1024
#define D  512
#define NH 8
#define DH 64

// ---------------- scratch ----------------
__device__ float g_h[BZ * LQ * D];               // fp32 h (exact, fixup + residual)
__device__ uint32_t g_hth[BZ * LQ * D / 2];      // half2 of h
__device__ uint32_t g_Wth[3 * D * D / 2];        // half2 of Wq,Wk,Wv
__device__ uint32_t g_Qh[BZ * LQ * D / 2];       // half2 Q, pre-scaled by 1/8
__device__ uint32_t g_Kh[BZ * LQ * D / 2];       // half2 K
__device__ float g_V[BZ * LQ * D];               // tf32 bits V
__device__ float g_norm[BZ * LQ];
__device__ unsigned long long g_mbits[(size_t)BZ * LQ * (LQ / 64)];  // bit=1: masked

// ---------------- helpers ----------------
__device__ __forceinline__ uint32_t f2tf(float f) {
    uint32_t u;
    asm("cvt.rna.tf32.f32 %0, %1;" : "=r"(u) : "f"(f));
    return u;
}
__device__ __forceinline__ uint32_t pack_h2(float a, float b) {
    __half2 h = __floats2half2_rn(a, b);
    return *(uint32_t*)&h;
}
// fp16 mma: D(16x8,f32) += A(16x16,f16 row) * B(16x8,f16 col)
__device__ __forceinline__ void mma16(float* d, const uint32_t* a, const uint32_t* b) {
    asm volatile(
        "mma.sync.aligned.m16n8k16.row.col.f32.f16.f16.f32 "
        "{%0,%1,%2,%3},{%4,%5,%6,%7},{%8,%9},{%0,%1,%2,%3};\n"
        : "+f"(d[0]), "+f"(d[1]), "+f"(d[2]), "+f"(d[3])
        : "r"(a[0]), "r"(a[1]), "r"(a[2]), "r"(a[3]), "r"(b[0]), "r"(b[1]));
}
// tf32 mma (PV path in attention)
__device__ __forceinline__ void mma8(float* d, const uint32_t* a, const uint32_t* b) {
    asm volatile(
        "mma.sync.aligned.m16n8k8.row.col.f32.tf32.tf32.f32 "
        "{%0,%1,%2,%3},{%4,%5,%6,%7},{%8,%9},{%0,%1,%2,%3};\n"
        : "+f"(d[0]), "+f"(d[1]), "+f"(d[2]), "+f"(d[3])
        : "r"(a[0]), "r"(a[1]), "r"(a[2]), "r"(a[3]), "r"(b[0]), "r"(b[1]));
}
__device__ __forceinline__ void cpasync16(uint32_t saddr, const void* g) {
    asm volatile("cp.async.cg.shared.global [%0], [%1], 16;" :: "r"(saddr), "l"(g));
}
#define CP_COMMIT() asm volatile("cp.async.commit_group;")
#define CP_WAIT0()  asm volatile("cp.async.wait_group 0;")
#define CP_WAIT1()  asm volatile("cp.async.wait_group 1;")

#define KPH 12                     // half2 words per row per k16 panel (8 data + 4 pad)
#define PANELH (128 * KPH)         // words per stage per matrix
#define GEMM_BLOCKS (4 * 64 * 3)   // 768
#define MASK_BLOCKS 36             // per batch
#define KW (D / 2)                 // 256 half2 words per full row

// ---------------- K1: prep (transpose + norms + fp16) fused with weight cvt ----------------
__global__ __launch_bounds__(128) void k_prep(
    const float* __restrict__ q,
    const float* __restrict__ W0, const float* __restrict__ W1, const float* __restrict__ W2) {
    if (blockIdx.x < BZ * LQ) {
        int row = blockIdx.x;              // r = i*BZ + b
        int i = row >> 3, b = row & 7;
        int tid = threadIdx.x, lane = tid & 31, wid = tid >> 5;
        float4 v = ((const float4*)(q + (size_t)row * D))[tid];
        size_t di = (size_t)(b * LQ + i) * (D / 4) + tid;
        ((float4*)g_h)[di] = v;
        uint2 w;
        w.x = pack_h2(v.x, v.y);
        w.y = pack_h2(v.z, v.w);
        ((uint2*)g_hth)[di] = w;
        float s = v.x * v.x + v.y * v.y + v.z * v.z + v.w * v.w;
        #pragma unroll
        for (int o = 16; o; o >>= 1) s += __shfl_xor_sync(0xffffffffu, s, o);
        __shared__ float ws[4];
        if (lane == 0) ws[wid] = s;
        __syncthreads();
        if (tid == 0)
            g_norm[b * LQ + i] = fmaxf(sqrtf(ws[0] + ws[1] + ws[2] + ws[3]), 1e-8f);
    } else {
        int idx = (blockIdx.x - BZ * LQ) * 128 + threadIdx.x;  // float4 units
        int z = idx >> 16, r = idx & 65535;
        const float* W = (z == 0) ? W0 : (z == 1) ? W1 : W2;
        float4 v = ((const float4*)W)[r];
        uint2 w;
        w.x = pack_h2(v.x, v.y);
        w.y = pack_h2(v.z, v.w);
        ((uint2*)g_Wth)[z * 65536 + r] = w;
    }
}

// ---------------- K2: FUSED [QKV fp16 GEMM | mask fp16 Gram], 3-stage cp.async ----------------
__global__ __launch_bounds__(256, 2) void k_gemm_mask(
    const float* __restrict__ seg,
    const float* __restrict__ b0, const float* __restrict__ b1, const float* __restrict__ b2)
{
    extern __shared__ __align__(16) uint32_t dsm[];
    uint32_t* As = dsm;                    // [3][128][KPH]
    uint32_t* Bs = dsm + 3 * PANELH;

    int tid = threadIdx.x, lane = tid & 31, wid = tid >> 5;
    int g = lane >> 2, q = lane & 3;
    int wm = wid >> 2, wn = wid & 3;
    int lrow = tid >> 1, lc = (tid & 1) * 4;     // each thread: one 16B chunk per matrix
    uint32_t sA = (uint32_t)__cvta_generic_to_shared(As + lrow * KPH + lc);
    uint32_t sB = (uint32_t)__cvta_generic_to_shared(Bs + lrow * KPH + lc);
    const int nP = D / 16;                 // 32 panels of k=16

    if (blockIdx.x < GEMM_BLOCKS) {
        // ---------- QKV GEMM path ----------
        int idx = blockIdx.x;
        int z = idx >> 8;                  // 256 blocks per matrix
        int r = idx & 255;
        int n0 = (r & 3) * 128, m0 = (r >> 2) * 128;
        const float* bias = (z == 0) ? b0 : (z == 1) ? b1 : b2;
        float oscale = (z == 0) ? 0.125f : 1.0f;

        const uint32_t* Ap = g_hth + (size_t)(m0 + lrow) * KW + lc;
        const uint32_t* Bp = g_Wth + (size_t)z * (D * D / 2) + (size_t)(n0 + lrow) * KW + lc;

        #pragma unroll
        for (int s = 0; s < 2; s++) {
            cpasync16(sA + s * PANELH * 4, Ap + s * 8);
            cpasync16(sB + s * PANELH * 4, Bp + s * 8);
            CP_COMMIT();
        }

        float acc[4][4][4] = {};
        for (int p = 0; p < nP; p++) {
            if (p + 1 < nP) CP_WAIT1(); else CP_WAIT0();
            __syncthreads();
            if (p + 2 < nP) {
                int st = (p + 2) % 3;
                cpasync16(sA + st * PANELH * 4, Ap + (p + 2) * 8);
                cpasync16(sB + st * PANELH * 4, Bp + (p + 2) * 8);
                CP_COMMIT();
            }
            const uint32_t* Ab = As + (p % 3) * PANELH;
            const uint32_t* Bb = Bs + (p % 3) * PANELH;
            uint32_t af[4][4], bf[4][2];
            #pragma unroll
            for (int mt = 0; mt < 4; mt++) {
                int mb = wm * 64 + mt * 16;
                af[mt][0] = Ab[(mb + g) * KPH + q];
                af[mt][1] = Ab[(mb + g + 8) * KPH + q];
                af[mt][2] = Ab[(mb + g) * KPH + q + 4];
                af[mt][3] = Ab[(mb + g + 8) * KPH + q + 4];
            }
            #pragma unroll
            for (int nt = 0; nt < 4; nt++) {
                int nb2 = wn * 32 + nt * 8 + g;
                bf[nt][0] = Bb[nb2 * KPH + q];
                bf[nt][1] = Bb[nb2 * KPH + q + 4];
            }
            #pragma unroll
            for (int mt = 0; mt < 4; mt++)
                #pragma unroll
                for (int nt = 0; nt < 4; nt++) mma16(acc[mt][nt], af[mt], bf[nt]);
        }

        #pragma unroll
        for (int mt = 0; mt < 4; mt++)
            #pragma unroll
            for (int h2 = 0; h2 < 2; h2++) {
                int m = m0 + wm * 64 + mt * 16 + g + h2 * 8;
                #pragma unroll
                for (int nt = 0; nt < 4; nt++) {
                    int n = n0 + wn * 32 + nt * 8 + 2 * q;
                    float x = (acc[mt][nt][h2 * 2 + 0] + bias[n]) * oscale;
                    float y = (acc[mt][nt][h2 * 2 + 1] + bias[n + 1]) * oscale;
                    if (z == 2) {
                        float2 v;
                        v.x = __uint_as_float(f2tf(x));
                        v.y = __uint_as_float(f2tf(y));
                        *(float2*)&g_V[(size_t)m * D + n] = v;
                    } else {
                        uint32_t* dst = (z == 0) ? g_Qh : g_Kh;
                        dst[(size_t)m * KW + (n >> 1)] = pack_h2(x, y);
                    }
                }
            }
    } else {
        // ---------- mask Gram path ----------
        __shared__ float si[128], ei[128], li[128], ni[128];
        __shared__ float sj[128], ej[128], lj[128], nj[128];
        int t = blockIdx.x - GEMM_BLOCKS;
        int b = t / MASK_BLOCKS;
        t -= b * MASK_BLOCKS;
        int it = 0;
        while ((it + 1) * (it + 2) / 2 <= t) it++;
        int jt = t - it * (it + 1) / 2;
        int i0 = it * 128, j0 = jt * 128;

        if (tid < 128) {
            int gi = b * LQ + i0 + tid;
            float c = seg[gi * 2], l = seg[gi * 2 + 1];
            si[tid] = c - 0.5f * l; ei[tid] = c + 0.5f * l; li[tid] = l;
            ni[tid] = g_norm[gi];
        } else {
            int tt = tid - 128;
            int gj = b * LQ + j0 + tt;
            float c = seg[gj * 2], l = seg[gj * 2 + 1];
            sj[tt] = c - 0.5f * l; ej[tt] = c + 0.5f * l; lj[tt] = l;
            nj[tt] = g_norm[gj];
        }

        const uint32_t* Tbase = g_hth + (size_t)b * LQ * KW;
        const float*    Abase = g_h   + (size_t)b * LQ * D;
        const uint32_t* Ap = Tbase + (size_t)(i0 + lrow) * KW + lc;
        const uint32_t* Bp = Tbase + (size_t)(j0 + lrow) * KW + lc;

        #pragma unroll
        for (int s = 0; s < 2; s++) {
            cpasync16(sA + s * PANELH * 4, Ap + s * 8);
            cpasync16(sB + s * PANELH * 4, Bp + s * 8);
            CP_COMMIT();
        }

        float acc[4][4][4] = {};
        for (int p = 0; p < nP; p++) {
            if (p + 1 < nP) CP_WAIT1(); else CP_WAIT0();
            __syncthreads();
            if (p + 2 < nP) {
                int st = (p + 2) % 3;
                cpasync16(sA + st * PANELH * 4, Ap + (p + 2) * 8);
                cpasync16(sB + st * PANELH * 4, Bp + (p + 2) * 8);
                CP_COMMIT();
            }
            const uint32_t* Ab = As + (p % 3) * PANELH;
            const uint32_t* Bb = Bs + (p % 3) * PANELH;
            uint32_t af[4][4], bf[4][2];
            #pragma unroll
            for (int mt = 0; mt < 4; mt++) {
                int mb = wm * 64 + mt * 16;
                af[mt][0] = Ab[(mb + g) * KPH + q];
                af[mt][1] = Ab[(mb + g + 8) * KPH + q];
                af[mt][2] = Ab[(mb + g) * KPH + q + 4];
                af[mt][3] = Ab[(mb + g + 8) * KPH + q + 4];
            }
            #pragma unroll
            for (int nt = 0; nt < 4; nt++) {
                int nb2 = wn * 32 + nt * 8 + g;
                bf[nt][0] = Bb[nb2 * KPH + q];
                bf[nt][1] = Bb[nb2 * KPH + q + 4];
            }
            #pragma unroll
            for (int mt = 0; mt < 4; mt++)
                #pragma unroll
                for (int nt = 0; nt < 4; nt++) mma16(acc[mt][nt], af[mt], bf[nt]);
        }
        __syncthreads();    // mainloop + all cp.async done; reuse dsm as byte staging

        unsigned char* Ms = (unsigned char*)dsm;            // [128][132]
        unsigned char* Ts = Ms + 128 * 132;                 // [128][132]

        #pragma unroll
        for (int mt = 0; mt < 4; mt++)
            #pragma unroll
            for (int h2 = 0; h2 < 2; h2++) {
                int ii = wm * 64 + mt * 16 + g + h2 * 8;
                int gi = i0 + ii;
                #pragma unroll
                for (int nt = 0; nt < 4; nt++) {
                    int jc = wn * 32 + nt * 8 + 2 * q;
                    #pragma unroll
                    for (int e = 0; e < 2; e++) {
                        int jj = jc + e, gj = j0 + jj;
                        float inv_nn = 1.f / (ni[ii] * nj[jj]);
                        float cosv = acc[mt][nt][h2 * 2 + e] * inv_nn;
                        if (fabsf(cosv - 0.2f) < 2e-3f) {
                            const float4* ra = (const float4*)(Abase + (size_t)gi * D);
                            const float4* rb = (const float4*)(Abase + (size_t)gj * D);
                            float dot = 0.f;
                            #pragma unroll 4
                            for (int k = 0; k < D / 4; k++) {
                                float4 x = ra[k], y = rb[k];
                                dot += x.x * y.x + x.y * y.y + x.z * y.z + x.w * y.w;
                            }
                            cosv = dot * inv_nn;
                        }
                        float inter = fmaxf(fminf(ei[ii], ej[jj]) - fmaxf(si[ii], sj[jj]), 0.f);
                        float uni   = li[ii] + lj[jj] - inter;
                        float iou   = inter / uni;
                        bool masked = (cosv <= 0.2f) || (iou > 0.2f && gi != gj);
                        unsigned char mb = masked ? 1 : 0;
                        Ms[ii * 132 + jj] = mb;
                        Ts[jj * 132 + ii] = mb;
                    }
                }
            }
        __syncthreads();

        {
            int row = tid >> 1, grp = tid & 1;
            const unsigned char* src = Ms + row * 132 + grp * 64;
            unsigned long long bits = 0ull;
            #pragma unroll 16
            for (int c = 0; c < 64; c++) bits |= (unsigned long long)src[c] << c;
            g_mbits[((size_t)b * LQ + i0 + row) * 16 + jt * 2 + grp] = bits;
            if (it != jt) {
                src = Ts + row * 132 + grp * 64;
                bits = 0ull;
                #pragma unroll 16
                for (int c = 0; c < 64; c++) bits |= (unsigned long long)src[c] << c;
                g_mbits[((size_t)b * LQ + j0 + row) * 16 + it * 2 + grp] = bits;
            }
        }
    }
}

// ---------------- K3: FA2 attention: fp16 QK^T + tf32 PV, bitmask tile skipping ----------------
#define ATPH 36                    // half2 words per Q/K row (32 data + 4 pad)
#define ATPV 68                    // tf32 words per V row
__global__ __launch_bounds__(256, 2) void k_attn(float* __restrict__ out) {
    extern __shared__ float sm[];
    uint32_t* Qs = (uint32_t*)sm;          // 128*ATPH half2, persistent
    uint32_t* Ks = Qs + 128 * ATPH;        // 64*ATPH half2
    uint32_t* Vs = Ks + 64 * ATPH;         // 64*ATPV tf32

    int i0 = blockIdx.x * 128, head = blockIdx.y, b = blockIdx.z;
    int tid = threadIdx.x, lane = tid & 31, wid = tid >> 5;
    int g = lane >> 2, q = lane & 3;
    const size_t baseh = (size_t)b * LQ * KW + head * (DH / 2);   // half2 rows
    const size_t basev = (size_t)b * LQ * D + head * DH;          // tf32 rows

    // stage Q tile (half2): 128 rows x 32 words = 1024 x 16B chunks
    #pragma unroll
    for (int s = 0; s < 4; s++) {
        int f = tid + s * 256;
        int r = f >> 3, w8 = (f & 7) << 2;
        cpasync16((uint32_t)__cvta_generic_to_shared(Qs + r * ATPH + w8),
                  &g_Qh[baseh + (size_t)(i0 + r) * KW + w8]);
    }
    CP_COMMIT();

    int lr = wid * 16;
    int gi0 = i0 + lr;
    float O[8][4] = {};
    float m0 = -1e30f, m1 = -1e30f, l0 = 0.f, l1 = 0.f;

    const unsigned long long* mb0 = g_mbits + ((size_t)b * LQ + gi0 + g) * 16;
    const unsigned long long* mb1 = g_mbits + ((size_t)b * LQ + gi0 + g + 8) * 16;

    for (int j = 0; j < 16; j++) {
        unsigned long long w0 = mb0[j], w1 = mb1[j];
        int any_un = ((w0 & w1) != 0xFFFFFFFFFFFFFFFFull);
        int blk_active = __syncthreads_or(any_un);
        if (!blk_active) continue;

        int j0 = j * 64;
        // K (half2): 64 rows x 32 words = 512 chunks; V (tf32): 64 x 64 words = 1024 chunks
        #pragma unroll
        for (int s = 0; s < 2; s++) {
            int f = tid + s * 256;
            int r = f >> 3, w8 = (f & 7) << 2;
            cpasync16((uint32_t)__cvta_generic_to_shared(Ks + r * ATPH + w8),
                      &g_Kh[baseh + (size_t)(j0 + r) * KW + w8]);
        }
        #pragma unroll
        for (int s = 0; s < 4; s++) {
            int f = tid + s * 256;
            int r = f >> 4, c4 = (f & 15) << 2;
            cpasync16((uint32_t)__cvta_generic_to_shared(Vs + r * ATPV + c4),
                      &g_V[basev + (size_t)(j0 + r) * D + c4]);
        }
        CP_COMMIT();
        CP_WAIT0();
        __syncthreads();

        unsigned wact = __ballot_sync(0xffffffffu, any_un);
        if (!wact) continue;

        // S = (Q/8) K^T : fp16, 4 k16 panels over dh=64
        float S[8][4] = {};
        #pragma unroll
        for (int kp = 0; kp < 4; kp++) {
            uint32_t af[4];
            af[0] = Qs[(lr + g) * ATPH + kp * 8 + q];
            af[1] = Qs[(lr + g + 8) * ATPH + kp * 8 + q];
            af[2] = Qs[(lr + g) * ATPH + kp * 8 + q + 4];
            af[3] = Qs[(lr + g + 8) * ATPH + kp * 8 + q + 4];
            uint32_t bf[8][2];
            #pragma unroll
            for (int nt = 0; nt < 8; nt++) {
                bf[nt][0] = Ks[(nt * 8 + g) * ATPH + kp * 8 + q];
                bf[nt][1] = Ks[(nt * 8 + g) * ATPH + kp * 8 + q + 4];
            }
            #pragma unroll
            for (int nt = 0; nt < 8; nt++) mma16(S[nt], af, bf[nt]);
        }

        #pragma unroll
        for (int nt = 0; nt < 8; nt++) {
            int c = nt * 8 + 2 * q;
            if ((w0 >> c) & 1)       S[nt][0] = -1e30f;
            if ((w0 >> (c + 1)) & 1) S[nt][1] = -1e30f;
            if ((w1 >> c) & 1)       S[nt][2] = -1e30f;
            if ((w1 >> (c + 1)) & 1) S[nt][3] = -1e30f;
        }

        float mx0 = -1e30f, mx1 = -1e30f;
        #pragma unroll
        for (int nt = 0; nt < 8; nt++) {
            mx0 = fmaxf(mx0, fmaxf(S[nt][0], S[nt][1]));
            mx1 = fmaxf(mx1, fmaxf(S[nt][2], S[nt][3]));
        }
        #pragma unroll
        for (int o = 1; o < 4; o <<= 1) {
            mx0 = fmaxf(mx0, __shfl_xor_sync(0xffffffffu, mx0, o));
            mx1 = fmaxf(mx1, __shfl_xor_sync(0xffffffffu, mx1, o));
        }
        float mn0 = fmaxf(m0, mx0), mn1 = fmaxf(m1, mx1);

        uint32_t (*P)[4] = (uint32_t(*)[4])S;
        float s0 = 0.f, s1 = 0.f;
        #pragma unroll
        for (int nt = 0; nt < 8; nt++) {
            float p00 = __expf(S[nt][0] - mn0), p01 = __expf(S[nt][1] - mn0);
            float p10 = __expf(S[nt][2] - mn1), p11 = __expf(S[nt][3] - mn1);
            s0 += p00 + p01; s1 += p10 + p11;
            P[nt][0] = f2tf(p00); P[nt][1] = f2tf(p01);
            P[nt][2] = f2tf(p10); P[nt][3] = f2tf(p11);
        }
        #pragma unroll
        for (int o = 1; o < 4; o <<= 1) {
            s0 += __shfl_xor_sync(0xffffffffu, s0, o);
            s1 += __shfl_xor_sync(0xffffffffu, s1, o);
        }
        float sc0 = __expf(m0 - mn0), sc1 = __expf(m1 - mn1);
        l0 = l0 * sc0 + s0; l1 = l1 * sc1 + s1;
        m0 = mn0; m1 = mn1;

        #pragma unroll
        for (int nt = 0; nt < 8; nt++) {
            O[nt][0] *= sc0; O[nt][1] *= sc0;
            O[nt][2] *= sc1; O[nt][3] *= sc1;
        }

        // O += P V (tf32, k-permuted fragments)
        #pragma unroll
        for (int kc = 0; kc < 8; kc++) {
            uint32_t af[4] = {P[kc][0], P[kc][2], P[kc][1], P[kc][3]};
            uint32_t bf[8][2];
            #pragma unroll
            for (int nt = 0; nt < 8; nt++) {
                bf[nt][0] = Vs[(kc * 8 + 2 * q) * ATPV + nt * 8 + g];
                bf[nt][1] = Vs[(kc * 8 + 2 * q + 1) * ATPV + nt * 8 + g];
            }
            #pragma unroll
            for (int nt = 0; nt < 8; nt++) mma8(O[nt], af, bf[nt]);
        }
    }

    float inv0 = 1.f / l0, inv1 = 1.f / l1;
    int r0 = gi0 + g, r1 = gi0 + g + 8;
    #pragma unroll
    for (int nt = 0; nt < 8; nt++) {
        int col = head * DH + nt * 8 + 2 * q;
        float2 h0 = *(const float2*)&g_h[((size_t)b * LQ + r0) * D + col];
        float2 h1 = *(const float2*)&g_h[((size_t)b * LQ + r1) * D + col];
        float2 o0, o1;
        o0.x = O[nt][0] * inv0 + h0.x; o0.y = O[nt][1] * inv0 + h0.y;
        o1.x = O[nt][2] * inv1 + h1.x; o1.y = O[nt][3] * inv1 + h1.y;
        *(float2*)&out[((size_t)r0 * BZ + b) * D + col] = o0;
        *(float2*)&out[((size_t)r1 * BZ + b) * D + col] = o1;
    }
}

// ---------------- host ----------------
extern "C" void kernel_launch(void* const* d_in, const int* in_sizes, int n_in,
                              void* d_out, int out_size) {
    const float* query = (const float*)d_in[0];
    const float* seg   = (const float*)d_in[1];
    const float* Wq    = (const float*)d_in[2];
    const float* bq    = (const float*)d_in[3];
    const float* Wk    = (const float*)d_in[4];
    const float* bk    = (const float*)d_in[5];
    const float* Wv    = (const float*)d_in[6];
    const float* bv    = (const float*)d_in[7];
    float* out = (float*)d_out;

    // prep (8192 blocks) + weight cvt (1536 blocks), fused
    k_prep<<<BZ * LQ + 3 * 65536 / 128, 128>>>(query, Wq, Wk, Wv);

    int smem_g = 6 * PANELH * (int)sizeof(uint32_t);   // 36864 B
    cudaFuncSetAttribute(k_gemm_mask, cudaFuncAttributeMaxDynamicSharedMemorySize, smem_g);
    k_gemm_mask<<<GEMM_BLOCKS + MASK_BLOCKS * BZ, 256, smem_g>>>(seg, bq, bk, bv);

    int smem_a = (128 * ATPH + 64 * ATPH + 64 * ATPV) * (int)sizeof(uint32_t);  // 45056 B
    cudaFuncSetAttribute(k_attn, cudaFuncAttributeMaxDynamicSharedMemorySize, smem_a);
    dim3 ga(LQ / 128, NH, BZ);            // (8, 8, 8)
    k_attn<<<ga, 256, smem_a>>>(out);
}

// round 13
// speedup vs baseline: 1.7206x; 1.0971x over previous
#include <cuda_runtime.h>
#include <cuda_fp16.h>
#include <stdint.h>
#include <math.h>

#define BZ 8
#define LQ 1024
#define D  512
#define NH 8
#define DH 64

// ---------------- scratch ----------------
__device__ float g_h[BZ * LQ * D];               // fp32 h (exact, fixup + residual)
__device__ uint32_t g_hth[BZ * LQ * D / 2];      // half2 of h
__device__ uint32_t g_Wth[3 * D * D / 2];        // half2 of Wq,Wk,Wv
__device__ uint32_t g_Qh[BZ * LQ * D / 2];       // half2 Q, pre-scaled by 1/8
__device__ uint32_t g_Kh[BZ * LQ * D / 2];       // half2 K
__device__ float g_V[BZ * LQ * D];               // tf32 bits V
__device__ float g_norm[BZ * LQ];
__device__ unsigned long long g_mbits[(size_t)BZ * LQ * (LQ / 64)];  // bit=1: masked

// ---------------- helpers ----------------
__device__ __forceinline__ uint32_t f2tf(float f) {
    uint32_t u;
    asm("cvt.rna.tf32.f32 %0, %1;" : "=r"(u) : "f"(f));
    return u;
}
__device__ __forceinline__ uint32_t pack_h2(float a, float b) {
    __half2 h = __floats2half2_rn(a, b);
    return *(uint32_t*)&h;
}
__device__ __forceinline__ void mma16(float* d, const uint32_t* a, const uint32_t* b) {
    asm volatile(
        "mma.sync.aligned.m16n8k16.row.col.f32.f16.f16.f32 "
        "{%0,%1,%2,%3},{%4,%5,%6,%7},{%8,%9},{%0,%1,%2,%3};\n"
        : "+f"(d[0]), "+f"(d[1]), "+f"(d[2]), "+f"(d[3])
        : "r"(a[0]), "r"(a[1]), "r"(a[2]), "r"(a[3]), "r"(b[0]), "r"(b[1]));
}
__device__ __forceinline__ void mma8(float* d, const uint32_t* a, const uint32_t* b) {
    asm volatile(
        "mma.sync.aligned.m16n8k8.row.col.f32.tf32.tf32.f32 "
        "{%0,%1,%2,%3},{%4,%5,%6,%7},{%8,%9},{%0,%1,%2,%3};\n"
        : "+f"(d[0]), "+f"(d[1]), "+f"(d[2]), "+f"(d[3])
        : "r"(a[0]), "r"(a[1]), "r"(a[2]), "r"(a[3]), "r"(b[0]), "r"(b[1]));
}
__device__ __forceinline__ void ldsm4(uint32_t* r, uint32_t addr) {
    asm volatile("ldmatrix.sync.aligned.m8n8.x4.shared.b16 {%0,%1,%2,%3}, [%4];"
        : "=r"(r[0]), "=r"(r[1]), "=r"(r[2]), "=r"(r[3]) : "r"(addr));
}
__device__ __forceinline__ void cpasync16(uint32_t saddr, const void* g) {
    asm volatile("cp.async.cg.shared.global [%0], [%1], 16;" :: "r"(saddr), "l"(g));
}
#define CP_COMMIT() asm volatile("cp.async.commit_group;")
#define CP_WAIT0()  asm volatile("cp.async.wait_group 0;")
#define CP_WAIT1()  asm volatile("cp.async.wait_group 1;")

#define KPH 12                     // half2 words per row per k16 panel (8 data + 4 pad)
#define PANELH (128 * KPH)         // words per stage per matrix
#define GEMM_BLOCKS (4 * 64 * 3)   // 768
#define MASK_BLOCKS 36             // per batch
#define KW (D / 2)                 // 256 half2 words per full row

// ---------------- K1: prep (transpose + norms + fp16) fused with weight cvt ----------------
__global__ __launch_bounds__(128) void k_prep(
    const float* __restrict__ q,
    const float* __restrict__ W0, const float* __restrict__ W1, const float* __restrict__ W2) {
    if (blockIdx.x < BZ * LQ) {
        int row = blockIdx.x;              // r = i*BZ + b
        int i = row >> 3, b = row & 7;
        int tid = threadIdx.x, lane = tid & 31, wid = tid >> 5;
        float4 v = ((const float4*)(q + (size_t)row * D))[tid];
        size_t di = (size_t)(b * LQ + i) * (D / 4) + tid;
        ((float4*)g_h)[di] = v;
        uint2 w;
        w.x = pack_h2(v.x, v.y);
        w.y = pack_h2(v.z, v.w);
        ((uint2*)g_hth)[di] = w;
        float s = v.x * v.x + v.y * v.y + v.z * v.z + v.w * v.w;
        #pragma unroll
        for (int o = 16; o; o >>= 1) s += __shfl_xor_sync(0xffffffffu, s, o);
        __shared__ float ws[4];
        if (lane == 0) ws[wid] = s;
        __syncthreads();
        if (tid == 0)
            g_norm[b * LQ + i] = fmaxf(sqrtf(ws[0] + ws[1] + ws[2] + ws[3]), 1e-8f);
    } else {
        int idx = (blockIdx.x - BZ * LQ) * 128 + threadIdx.x;  // float4 units
        int z = idx >> 16, r = idx & 65535;
        const float* W = (z == 0) ? W0 : (z == 1) ? W1 : W2;
        float4 v = ((const float4*)W)[r];
        uint2 w;
        w.x = pack_h2(v.x, v.y);
        w.y = pack_h2(v.z, v.w);
        ((uint2*)g_Wth)[z * 65536 + r] = w;
    }
}

// ---------------- K2: FUSED [QKV fp16 GEMM | mask fp16 Gram], ldmatrix fragments ----------------
__global__ __launch_bounds__(256, 2) void k_gemm_mask(
    const float* __restrict__ seg,
    const float* __restrict__ b0, const float* __restrict__ b1, const float* __restrict__ b2)
{
    extern __shared__ __align__(16) uint32_t dsm[];
    uint32_t* As = dsm;                    // [3][128][KPH]
    uint32_t* Bs = dsm + 3 * PANELH;

    int tid = threadIdx.x, lane = tid & 31, wid = tid >> 5;
    int g = lane >> 2, q = lane & 3;
    int wm = wid >> 2, wn = wid & 3;
    int lrow = tid >> 1, lc = (tid & 1) * 4;     // one 16B chunk per matrix per thread
    uint32_t sA = (uint32_t)__cvta_generic_to_shared(As + lrow * KPH + lc);
    uint32_t sB = (uint32_t)__cvta_generic_to_shared(Bs + lrow * KPH + lc);
    uint32_t AsS = (uint32_t)__cvta_generic_to_shared(As);
    uint32_t BsS = (uint32_t)__cvta_generic_to_shared(Bs);
    const int nP = D / 16;                 // 32 panels of k=16

    // ldmatrix lane-address components
    int laA  = ((lane & 15) * KPH + (lane >> 4) * 4) * 4;             // A tiles
    int lbR  = lane & 7;                                              // B tiles
    int lbSel = (lane >> 4);                                          // nt within pair
    int lbKw = ((lane >> 3) & 1) * 4;

    if (blockIdx.x < GEMM_BLOCKS) {
        // ---------- QKV GEMM path ----------
        int idx = blockIdx.x;
        int z = idx >> 8;
        int r = idx & 255;
        int n0 = (r & 3) * 128, m0 = (r >> 2) * 128;
        const float* bias = (z == 0) ? b0 : (z == 1) ? b1 : b2;
        float oscale = (z == 0) ? 0.125f : 1.0f;

        const uint32_t* Ap = g_hth + (size_t)(m0 + lrow) * KW + lc;
        const uint32_t* Bp = g_Wth + (size_t)z * (D * D / 2) + (size_t)(n0 + lrow) * KW + lc;

        #pragma unroll
        for (int s = 0; s < 2; s++) {
            cpasync16(sA + s * PANELH * 4, Ap + s * 8);
            cpasync16(sB + s * PANELH * 4, Bp + s * 8);
            CP_COMMIT();
        }

        float acc[4][4][4] = {};
        for (int p = 0; p < nP; p++) {
            if (p + 1 < nP) CP_WAIT1(); else CP_WAIT0();
            __syncthreads();
            if (p + 2 < nP) {
                int st = (p + 2) % 3;
                cpasync16(sA + st * PANELH * 4, Ap + (p + 2) * 8);
                cpasync16(sB + st * PANELH * 4, Bp + (p + 2) * 8);
                CP_COMMIT();
            }
            uint32_t AbS = AsS + (p % 3) * PANELH * 4;
            uint32_t BbS = BsS + (p % 3) * PANELH * 4;
            uint32_t af[4][4], bf[4][2];
            #pragma unroll
            for (int mt = 0; mt < 4; mt++)
                ldsm4(af[mt], AbS + (wm * 64 + mt * 16) * KPH * 4 + laA);
            #pragma unroll
            for (int p2 = 0; p2 < 2; p2++) {
                int nb = wn * 32 + (2 * p2 + lbSel) * 8 + lbR;
                uint32_t tmp[4];
                ldsm4(tmp, BbS + (nb * KPH + lbKw) * 4);
                bf[2 * p2][0] = tmp[0]; bf[2 * p2][1] = tmp[1];
                bf[2 * p2 + 1][0] = tmp[2]; bf[2 * p2 + 1][1] = tmp[3];
            }
            #pragma unroll
            for (int mt = 0; mt < 4; mt++)
                #pragma unroll
                for (int nt = 0; nt < 4; nt++) mma16(acc[mt][nt], af[mt], bf[nt]);
        }

        #pragma unroll
        for (int mt = 0; mt < 4; mt++)
            #pragma unroll
            for (int h2 = 0; h2 < 2; h2++) {
                int m = m0 + wm * 64 + mt * 16 + g + h2 * 8;
                #pragma unroll
                for (int nt = 0; nt < 4; nt++) {
                    int n = n0 + wn * 32 + nt * 8 + 2 * q;
                    float x = (acc[mt][nt][h2 * 2 + 0] + bias[n]) * oscale;
                    float y = (acc[mt][nt][h2 * 2 + 1] + bias[n + 1]) * oscale;
                    if (z == 2) {
                        float2 v;
                        v.x = __uint_as_float(f2tf(x));
                        v.y = __uint_as_float(f2tf(y));
                        *(float2*)&g_V[(size_t)m * D + n] = v;
                    } else {
                        uint32_t* dst = (z == 0) ? g_Qh : g_Kh;
                        dst[(size_t)m * KW + (n >> 1)] = pack_h2(x, y);
                    }
                }
            }
    } else {
        // ---------- mask Gram path ----------
        __shared__ float si[128], ei[128], li[128], ni[128];
        __shared__ float sj[128], ej[128], lj[128], nj[128];
        int t = blockIdx.x - GEMM_BLOCKS;
        int b = t / MASK_BLOCKS;
        t -= b * MASK_BLOCKS;
        int it = 0;
        while ((it + 1) * (it + 2) / 2 <= t) it++;
        int jt = t - it * (it + 1) / 2;
        int i0 = it * 128, j0 = jt * 128;

        if (tid < 128) {
            int gi = b * LQ + i0 + tid;
            float c = seg[gi * 2], l = seg[gi * 2 + 1];
            si[tid] = c - 0.5f * l; ei[tid] = c + 0.5f * l; li[tid] = l;
            ni[tid] = g_norm[gi];
        } else {
            int tt = tid - 128;
            int gj = b * LQ + j0 + tt;
            float c = seg[gj * 2], l = seg[gj * 2 + 1];
            sj[tt] = c - 0.5f * l; ej[tt] = c + 0.5f * l; lj[tt] = l;
            nj[tt] = g_norm[gj];
        }

        const uint32_t* Tbase = g_hth + (size_t)b * LQ * KW;
        const float*    Abase = g_h   + (size_t)b * LQ * D;
        const uint32_t* Ap = Tbase + (size_t)(i0 + lrow) * KW + lc;
        const uint32_t* Bp = Tbase + (size_t)(j0 + lrow) * KW + lc;

        #pragma unroll
        for (int s = 0; s < 2; s++) {
            cpasync16(sA + s * PANELH * 4, Ap + s * 8);
            cpasync16(sB + s * PANELH * 4, Bp + s * 8);
            CP_COMMIT();
        }

        float acc[4][4][4] = {};
        for (int p = 0; p < nP; p++) {
            if (p + 1 < nP) CP_WAIT1(); else CP_WAIT0();
            __syncthreads();
            if (p + 2 < nP) {
                int st = (p + 2) % 3;
                cpasync16(sA + st * PANELH * 4, Ap + (p + 2) * 8);
                cpasync16(sB + st * PANELH * 4, Bp + (p + 2) * 8);
                CP_COMMIT();
            }
            uint32_t AbS = AsS + (p % 3) * PANELH * 4;
            uint32_t BbS = BsS + (p % 3) * PANELH * 4;
            uint32_t af[4][4], bf[4][2];
            #pragma unroll
            for (int mt = 0; mt < 4; mt++)
                ldsm4(af[mt], AbS + (wm * 64 + mt * 16) * KPH * 4 + laA);
            #pragma unroll
            for (int p2 = 0; p2 < 2; p2++) {
                int nb = wn * 32 + (2 * p2 + lbSel) * 8 + lbR;
                uint32_t tmp[4];
                ldsm4(tmp, BbS + (nb * KPH + lbKw) * 4);
                bf[2 * p2][0] = tmp[0]; bf[2 * p2][1] = tmp[1];
                bf[2 * p2 + 1][0] = tmp[2]; bf[2 * p2 + 1][1] = tmp[3];
            }
            #pragma unroll
            for (int mt = 0; mt < 4; mt++)
                #pragma unroll
                for (int nt = 0; nt < 4; nt++) mma16(acc[mt][nt], af[mt], bf[nt]);
        }
        __syncthreads();    // mainloop + all cp.async done; reuse dsm as byte staging

        unsigned char* Ms = (unsigned char*)dsm;            // [128][132]
        unsigned char* Ts = Ms + 128 * 132;                 // [128][132]

        #pragma unroll
        for (int mt = 0; mt < 4; mt++)
            #pragma unroll
            for (int h2 = 0; h2 < 2; h2++) {
                int ii = wm * 64 + mt * 16 + g + h2 * 8;
                int gi = i0 + ii;
                #pragma unroll
                for (int nt = 0; nt < 4; nt++) {
                    int jc = wn * 32 + nt * 8 + 2 * q;
                    #pragma unroll
                    for (int e = 0; e < 2; e++) {
                        int jj = jc + e, gj = j0 + jj;
                        float inv_nn = 1.f / (ni[ii] * nj[jj]);
                        float cosv = acc[mt][nt][h2 * 2 + e] * inv_nn;
                        if (fabsf(cosv - 0.2f) < 2e-3f) {
                            const float4* ra = (const float4*)(Abase + (size_t)gi * D);
                            const float4* rb = (const float4*)(Abase + (size_t)gj * D);
                            float dot = 0.f;
                            #pragma unroll 4
                            for (int k = 0; k < D / 4; k++) {
                                float4 x = ra[k], y = rb[k];
                                dot += x.x * y.x + x.y * y.y + x.z * y.z + x.w * y.w;
                            }
                            cosv = dot * inv_nn;
                        }
                        float inter = fmaxf(fminf(ei[ii], ej[jj]) - fmaxf(si[ii], sj[jj]), 0.f);
                        float uni   = li[ii] + lj[jj] - inter;
                        float iou   = inter / uni;
                        bool masked = (cosv <= 0.2f) || (iou > 0.2f && gi != gj);
                        unsigned char mb = masked ? 1 : 0;
                        Ms[ii * 132 + jj] = mb;
                        Ts[jj * 132 + ii] = mb;
                    }
                }
            }
        __syncthreads();

        {
            int row = tid >> 1, grp = tid & 1;
            const unsigned char* src = Ms + row * 132 + grp * 64;
            unsigned long long bits = 0ull;
            #pragma unroll 16
            for (int c = 0; c < 64; c++) bits |= (unsigned long long)src[c] << c;
            g_mbits[((size_t)b * LQ + i0 + row) * 16 + jt * 2 + grp] = bits;
            if (it != jt) {
                src = Ts + row * 132 + grp * 64;
                bits = 0ull;
                #pragma unroll 16
                for (int c = 0; c < 64; c++) bits |= (unsigned long long)src[c] << c;
                g_mbits[((size_t)b * LQ + j0 + row) * 16 + it * 2 + grp] = bits;
            }
        }
    }
}

// ---------------- K3: FA2 attention: fp16 QK^T (ldmatrix) + tf32 PV ----------------
#define ATPH 36                    // half2 words per Q/K row (32 data + 4 pad)
#define ATPV 68                    // tf32 words per V row
__global__ __launch_bounds__(256, 2) void k_attn(float* __restrict__ out) {
    extern __shared__ float sm[];
    uint32_t* Qs = (uint32_t*)sm;          // 128*ATPH half2, persistent
    uint32_t* Ks = Qs + 128 * ATPH;        // 64*ATPH half2
    uint32_t* Vs = Ks + 64 * ATPH;         // 64*ATPV tf32

    int i0 = blockIdx.x * 128, head = blockIdx.y, b = blockIdx.z;
    int tid = threadIdx.x, lane = tid & 31, wid = tid >> 5;
    int g = lane >> 2, q = lane & 3;
    const size_t baseh = (size_t)b * LQ * KW + head * (DH / 2);
    const size_t basev = (size_t)b * LQ * D + head * DH;
    uint32_t QsS = (uint32_t)__cvta_generic_to_shared(Qs);
    uint32_t KsS = (uint32_t)__cvta_generic_to_shared(Ks);

    // ldmatrix lane components
    int laA  = ((lane & 15) * ATPH + (lane >> 4) * 4) * 4;
    int lbR  = lane & 7;
    int lbSel = (lane >> 4);
    int lbKw = ((lane >> 3) & 1) * 4;

    #pragma unroll
    for (int s = 0; s < 4; s++) {
        int f = tid + s * 256;
        int r = f >> 3, w8 = (f & 7) << 2;
        cpasync16((uint32_t)__cvta_generic_to_shared(Qs + r * ATPH + w8),
                  &g_Qh[baseh + (size_t)(i0 + r) * KW + w8]);
    }
    CP_COMMIT();

    int lr = wid * 16;
    int gi0 = i0 + lr;
    float O[8][4] = {};
    float m0 = -1e30f, m1 = -1e30f, l0 = 0.f, l1 = 0.f;

    const unsigned long long* mb0 = g_mbits + ((size_t)b * LQ + gi0 + g) * 16;
    const unsigned long long* mb1 = g_mbits + ((size_t)b * LQ + gi0 + g + 8) * 16;

    for (int j = 0; j < 16; j++) {
        unsigned long long w0 = mb0[j], w1 = mb1[j];
        int any_un = ((w0 & w1) != 0xFFFFFFFFFFFFFFFFull);
        int blk_active = __syncthreads_or(any_un);
        if (!blk_active) continue;

        int j0 = j * 64;
        #pragma unroll
        for (int s = 0; s < 2; s++) {
            int f = tid + s * 256;
            int r = f >> 3, w8 = (f & 7) << 2;
            cpasync16((uint32_t)__cvta_generic_to_shared(Ks + r * ATPH + w8),
                      &g_Kh[baseh + (size_t)(j0 + r) * KW + w8]);
        }
        #pragma unroll
        for (int s = 0; s < 4; s++) {
            int f = tid + s * 256;
            int r = f >> 4, c4 = (f & 15) << 2;
            cpasync16((uint32_t)__cvta_generic_to_shared(Vs + r * ATPV + c4),
                      &g_V[basev + (size_t)(j0 + r) * D + c4]);
        }
        CP_COMMIT();
        CP_WAIT0();
        __syncthreads();

        unsigned wact = __ballot_sync(0xffffffffu, any_un);
        if (!wact) continue;

        // S = (Q/8) K^T : fp16, 4 k16 panels over dh=64
        float S[8][4] = {};
        #pragma unroll
        for (int kp = 0; kp < 4; kp++) {
            uint32_t af[4];
            ldsm4(af, QsS + lr * ATPH * 4 + kp * 32 + laA);
            uint32_t bf[8][2];
            #pragma unroll
            for (int p2 = 0; p2 < 4; p2++) {
                int nb = (2 * p2 + lbSel) * 8 + lbR;
                uint32_t tmp[4];
                ldsm4(tmp, KsS + (nb * ATPH + kp * 8 + lbKw) * 4);
                bf[2 * p2][0] = tmp[0]; bf[2 * p2][1] = tmp[1];
                bf[2 * p2 + 1][0] = tmp[2]; bf[2 * p2 + 1][1] = tmp[3];
            }
            #pragma unroll
            for (int nt = 0; nt < 8; nt++) mma16(S[nt], af, bf[nt]);
        }

        #pragma unroll
        for (int nt = 0; nt < 8; nt++) {
            int c = nt * 8 + 2 * q;
            if ((w0 >> c) & 1)       S[nt][0] = -1e30f;
            if ((w0 >> (c + 1)) & 1) S[nt][1] = -1e30f;
            if ((w1 >> c) & 1)       S[nt][2] = -1e30f;
            if ((w1 >> (c + 1)) & 1) S[nt][3] = -1e30f;
        }

        float mx0 = -1e30f, mx1 = -1e30f;
        #pragma unroll
        for (int nt = 0; nt < 8; nt++) {
            mx0 = fmaxf(mx0, fmaxf(S[nt][0], S[nt][1]));
            mx1 = fmaxf(mx1, fmaxf(S[nt][2], S[nt][3]));
        }
        #pragma unroll
        for (int o = 1; o < 4; o <<= 1) {
            mx0 = fmaxf(mx0, __shfl_xor_sync(0xffffffffu, mx0, o));
            mx1 = fmaxf(mx1, __shfl_xor_sync(0xffffffffu, mx1, o));
        }
        float mn0 = fmaxf(m0, mx0), mn1 = fmaxf(m1, mx1);

        uint32_t (*P)[4] = (uint32_t(*)[4])S;
        float s0 = 0.f, s1 = 0.f;
        #pragma unroll
        for (int nt = 0; nt < 8; nt++) {
            float p00 = __expf(S[nt][0] - mn0), p01 = __expf(S[nt][1] - mn0);
            float p10 = __expf(S[nt][2] - mn1), p11 = __expf(S[nt][3] - mn1);
            s0 += p00 + p01; s1 += p10 + p11;
            P[nt][0] = f2tf(p00); P[nt][1] = f2tf(p01);
            P[nt][2] = f2tf(p10); P[nt][3] = f2tf(p11);
        }
        #pragma unroll
        for (int o = 1; o < 4; o <<= 1) {
            s0 += __shfl_xor_sync(0xffffffffu, s0, o);
            s1 += __shfl_xor_sync(0xffffffffu, s1, o);
        }
        float sc0 = __expf(m0 - mn0), sc1 = __expf(m1 - mn1);
        l0 = l0 * sc0 + s0; l1 = l1 * sc1 + s1;
        m0 = mn0; m1 = mn1;

        #pragma unroll
        for (int nt = 0; nt < 8; nt++) {
            O[nt][0] *= sc0; O[nt][1] *= sc0;
            O[nt][2] *= sc1; O[nt][3] *= sc1;
        }

        // O += P V (tf32, k-permuted fragments)
        #pragma unroll
        for (int kc = 0; kc < 8; kc++) {
            uint32_t af[4] = {P[kc][0], P[kc][2], P[kc][1], P[kc][3]};
            uint32_t bf[8][2];
            #pragma unroll
            for (int nt = 0; nt < 8; nt++) {
                bf[nt][0] = Vs[(kc * 8 + 2 * q) * ATPV + nt * 8 + g];
                bf[nt][1] = Vs[(kc * 8 + 2 * q + 1) * ATPV + nt * 8 + g];
            }
            #pragma unroll
            for (int nt = 0; nt < 8; nt++) mma8(O[nt], af, bf[nt]);
        }
    }

    float inv0 = 1.f / l0, inv1 = 1.f / l1;
    int r0 = gi0 + g, r1 = gi0 + g + 8;
    #pragma unroll
    for (int nt = 0; nt < 8; nt++) {
        int col = head * DH + nt * 8 + 2 * q;
        float2 h0 = *(const float2*)&g_h[((size_t)b * LQ + r0) * D + col];
        float2 h1 = *(const float2*)&g_h[((size_t)b * LQ + r1) * D + col];
        float2 o0, o1;
        o0.x = O[nt][0] * inv0 + h0.x; o0.y = O[nt][1] * inv0 + h0.y;
        o1.x = O[nt][2] * inv1 + h1.x; o1.y = O[nt][3] * inv1 + h1.y;
        *(float2*)&out[((size_t)r0 * BZ + b) * D + col] = o0;
        *(float2*)&out[((size_t)r1 * BZ + b) * D + col] = o1;
    }
}

// ---------------- host ----------------
extern "C" void kernel_launch(void* const* d_in, const int* in_sizes, int n_in,
                              void* d_out, int out_size) {
    const float* query = (const float*)d_in[0];
    const float* seg   = (const float*)d_in[1];
    const float* Wq    = (const float*)d_in[2];
    const float* bq    = (const float*)d_in[3];
    const float* Wk    = (const float*)d_in[4];
    const float* bk    = (const float*)d_in[5];
    const float* Wv    = (const float*)d_in[6];
    const float* bv    = (const float*)d_in[7];
    float* out = (float*)d_out;

    k_prep<<<BZ * LQ + 3 * 65536 / 128, 128>>>(query, Wq, Wk, Wv);

    int smem_g = 6 * PANELH * (int)sizeof(uint32_t);   // 36864 B
    cudaFuncSetAttribute(k_gemm_mask, cudaFuncAttributeMaxDynamicSharedMemorySize, smem_g);
    k_gemm_mask<<<GEMM_BLOCKS + MASK_BLOCKS * BZ, 256, smem_g>>>(seg, bq, bk, bv);

    int smem_a = (128 * ATPH + 64 * ATPH + 64 * ATPV) * (int)sizeof(uint32_t);  // 45056 B
    cudaFuncSetAttribute(k_attn, cudaFuncAttributeMaxDynamicSharedMemorySize, smem_a);
    dim3 ga(LQ / 128, NH, BZ);            // (8, 8, 8)
    k_attn<<<ga, 256, smem_a>>>(out);
}

// round 14
// speedup vs baseline: 1.7909x; 1.0409x over previous
#include <cuda_runtime.h>
#include <cuda_fp16.h>
#include <stdint.h>
#include <math.h>

#define BZ 8
#define LQ 1024
#define D  512
#define NH 8
#define DH 64

// ---------------- scratch ----------------
__device__ float g_h[BZ * LQ * D];               // fp32 h (exact, fixup + residual)
__device__ uint32_t g_hth[BZ * LQ * D / 2];      // half2 of h
__device__ uint32_t g_Wth[3 * D * D / 2];        // half2 of Wq,Wk,Wv
__device__ uint32_t g_Qh[BZ * LQ * D / 2];       // half2 Q, pre-scaled by 1/8
__device__ uint32_t g_Kh[BZ * LQ * D / 2];       // half2 K
__device__ uint32_t g_Vh[BZ * LQ * D / 2];       // half2 V
__device__ float g_norm[BZ * LQ];
__device__ unsigned long long g_mbits[(size_t)BZ * LQ * (LQ / 64)];  // bit=1: masked

// ---------------- helpers ----------------
__device__ __forceinline__ uint32_t pack_h2(float a, float b) {
    __half2 h = __floats2half2_rn(a, b);
    return *(uint32_t*)&h;
}
__device__ __forceinline__ void mma16(float* d, const uint32_t* a, const uint32_t* b) {
    asm volatile(
        "mma.sync.aligned.m16n8k16.row.col.f32.f16.f16.f32 "
        "{%0,%1,%2,%3},{%4,%5,%6,%7},{%8,%9},{%0,%1,%2,%3};\n"
        : "+f"(d[0]), "+f"(d[1]), "+f"(d[2]), "+f"(d[3])
        : "r"(a[0]), "r"(a[1]), "r"(a[2]), "r"(a[3]), "r"(b[0]), "r"(b[1]));
}
__device__ __forceinline__ void ldsm4(uint32_t* r, uint32_t addr) {
    asm volatile("ldmatrix.sync.aligned.m8n8.x4.shared.b16 {%0,%1,%2,%3}, [%4];"
        : "=r"(r[0]), "=r"(r[1]), "=r"(r[2]), "=r"(r[3]) : "r"(addr));
}
__device__ __forceinline__ void ldsm4t(uint32_t* r, uint32_t addr) {
    asm volatile("ldmatrix.sync.aligned.m8n8.x4.trans.shared.b16 {%0,%1,%2,%3}, [%4];"
        : "=r"(r[0]), "=r"(r[1]), "=r"(r[2]), "=r"(r[3]) : "r"(addr));
}
__device__ __forceinline__ void cpasync16(uint32_t saddr, const void* g) {
    asm volatile("cp.async.cg.shared.global [%0], [%1], 16;" :: "r"(saddr), "l"(g));
}
#define CP_COMMIT() asm volatile("cp.async.commit_group;")
#define CP_WAIT0()  asm volatile("cp.async.wait_group 0;")
#define CP_WAIT1()  asm volatile("cp.async.wait_group 1;")

#define KPH 12                     // half2 words per row per k16 panel (8 data + 4 pad)
#define PANELH (128 * KPH)         // words per stage per matrix
#define GEMM_BLOCKS (4 * 64 * 3)   // 768
#define MASK_BLOCKS 36             // per batch
#define KW (D / 2)                 // 256 half2 words per full row

// ---------------- K1: prep (transpose + norms + fp16) fused with weight cvt ----------------
__global__ __launch_bounds__(128) void k_prep(
    const float* __restrict__ q,
    const float* __restrict__ W0, const float* __restrict__ W1, const float* __restrict__ W2) {
    if (blockIdx.x < BZ * LQ) {
        int row = blockIdx.x;              // r = i*BZ + b
        int i = row >> 3, b = row & 7;
        int tid = threadIdx.x, lane = tid & 31, wid = tid >> 5;
        float4 v = ((const float4*)(q + (size_t)row * D))[tid];
        size_t di = (size_t)(b * LQ + i) * (D / 4) + tid;
        ((float4*)g_h)[di] = v;
        uint2 w;
        w.x = pack_h2(v.x, v.y);
        w.y = pack_h2(v.z, v.w);
        ((uint2*)g_hth)[di] = w;
        float s = v.x * v.x + v.y * v.y + v.z * v.z + v.w * v.w;
        #pragma unroll
        for (int o = 16; o; o >>= 1) s += __shfl_xor_sync(0xffffffffu, s, o);
        __shared__ float ws[4];
        if (lane == 0) ws[wid] = s;
        __syncthreads();
        if (tid == 0)
            g_norm[b * LQ + i] = fmaxf(sqrtf(ws[0] + ws[1] + ws[2] + ws[3]), 1e-8f);
    } else {
        int idx = (blockIdx.x - BZ * LQ) * 128 + threadIdx.x;  // float4 units
        int z = idx >> 16, r = idx & 65535;
        const float* W = (z == 0) ? W0 : (z == 1) ? W1 : W2;
        float4 v = ((const float4*)W)[r];
        uint2 w;
        w.x = pack_h2(v.x, v.y);
        w.y = pack_h2(v.z, v.w);
        ((uint2*)g_Wth)[z * 65536 + r] = w;
    }
}

// ---------------- K2: FUSED [QKV fp16 GEMM | mask fp16 Gram], ldmatrix fragments ----------------
__global__ __launch_bounds__(256, 2) void k_gemm_mask(
    const float* __restrict__ seg,
    const float* __restrict__ b0, const float* __restrict__ b1, const float* __restrict__ b2)
{
    extern __shared__ __align__(16) uint32_t dsm[];
    uint32_t* As = dsm;                    // [3][128][KPH]
    uint32_t* Bs = dsm + 3 * PANELH;

    int tid = threadIdx.x, lane = tid & 31, wid = tid >> 5;
    int g = lane >> 2, q = lane & 3;
    int wm = wid >> 2, wn = wid & 3;
    int lrow = tid >> 1, lc = (tid & 1) * 4;     // one 16B chunk per matrix per thread
    uint32_t sA = (uint32_t)__cvta_generic_to_shared(As + lrow * KPH + lc);
    uint32_t sB = (uint32_t)__cvta_generic_to_shared(Bs + lrow * KPH + lc);
    uint32_t AsS = (uint32_t)__cvta_generic_to_shared(As);
    uint32_t BsS = (uint32_t)__cvta_generic_to_shared(Bs);
    const int nP = D / 16;                 // 32 panels of k=16

    // ldmatrix lane-address components
    int laA  = ((lane & 15) * KPH + (lane >> 4) * 4) * 4;             // A tiles
    int lbR  = lane & 7;
    int lbSel = (lane >> 4);
    int lbKw = ((lane >> 3) & 1) * 4;

    if (blockIdx.x < GEMM_BLOCKS) {
        // ---------- QKV GEMM path ----------
        int idx = blockIdx.x;
        int z = idx >> 8;
        int r = idx & 255;
        int n0 = (r & 3) * 128, m0 = (r >> 2) * 128;
        const float* bias = (z == 0) ? b0 : (z == 1) ? b1 : b2;
        float oscale = (z == 0) ? 0.125f : 1.0f;

        const uint32_t* Ap = g_hth + (size_t)(m0 + lrow) * KW + lc;
        const uint32_t* Bp = g_Wth + (size_t)z * (D * D / 2) + (size_t)(n0 + lrow) * KW + lc;

        #pragma unroll
        for (int s = 0; s < 2; s++) {
            cpasync16(sA + s * PANELH * 4, Ap + s * 8);
            cpasync16(sB + s * PANELH * 4, Bp + s * 8);
            CP_COMMIT();
        }

        float acc[4][4][4] = {};
        for (int p = 0; p < nP; p++) {
            if (p + 1 < nP) CP_WAIT1(); else CP_WAIT0();
            __syncthreads();
            if (p + 2 < nP) {
                int st = (p + 2) % 3;
                cpasync16(sA + st * PANELH * 4, Ap + (p + 2) * 8);
                cpasync16(sB + st * PANELH * 4, Bp + (p + 2) * 8);
                CP_COMMIT();
            }
            uint32_t AbS = AsS + (p % 3) * PANELH * 4;
            uint32_t BbS = BsS + (p % 3) * PANELH * 4;
            uint32_t af[4][4], bf[4][2];
            #pragma unroll
            for (int mt = 0; mt < 4; mt++)
                ldsm4(af[mt], AbS + (wm * 64 + mt * 16) * KPH * 4 + laA);
            #pragma unroll
            for (int p2 = 0; p2 < 2; p2++) {
                int nb = wn * 32 + (2 * p2 + lbSel) * 8 + lbR;
                uint32_t tmp[4];
                ldsm4(tmp, BbS + (nb * KPH + lbKw) * 4);
                bf[2 * p2][0] = tmp[0]; bf[2 * p2][1] = tmp[1];
                bf[2 * p2 + 1][0] = tmp[2]; bf[2 * p2 + 1][1] = tmp[3];
            }
            #pragma unroll
            for (int mt = 0; mt < 4; mt++)
                #pragma unroll
                for (int nt = 0; nt < 4; nt++) mma16(acc[mt][nt], af[mt], bf[nt]);
        }

        #pragma unroll
        for (int mt = 0; mt < 4; mt++)
            #pragma unroll
            for (int h2 = 0; h2 < 2; h2++) {
                int m = m0 + wm * 64 + mt * 16 + g + h2 * 8;
                #pragma unroll
                for (int nt = 0; nt < 4; nt++) {
                    int n = n0 + wn * 32 + nt * 8 + 2 * q;
                    float x = (acc[mt][nt][h2 * 2 + 0] + bias[n]) * oscale;
                    float y = (acc[mt][nt][h2 * 2 + 1] + bias[n + 1]) * oscale;
                    uint32_t* dst = (z == 0) ? g_Qh : (z == 1) ? g_Kh : g_Vh;
                    dst[(size_t)m * KW + (n >> 1)] = pack_h2(x, y);
                }
            }
    } else {
        // ---------- mask Gram path ----------
        __shared__ float si[128], ei[128], li[128], ni[128];
        __shared__ float sj[128], ej[128], lj[128], nj[128];
        int t = blockIdx.x - GEMM_BLOCKS;
        int b = t / MASK_BLOCKS;
        t -= b * MASK_BLOCKS;
        int it = 0;
        while ((it + 1) * (it + 2) / 2 <= t) it++;
        int jt = t - it * (it + 1) / 2;
        int i0 = it * 128, j0 = jt * 128;

        if (tid < 128) {
            int gi = b * LQ + i0 + tid;
            float c = seg[gi * 2], l = seg[gi * 2 + 1];
            si[tid] = c - 0.5f * l; ei[tid] = c + 0.5f * l; li[tid] = l;
            ni[tid] = g_norm[gi];
        } else {
            int tt = tid - 128;
            int gj = b * LQ + j0 + tt;
            float c = seg[gj * 2], l = seg[gj * 2 + 1];
            sj[tt] = c - 0.5f * l; ej[tt] = c + 0.5f * l; lj[tt] = l;
            nj[tt] = g_norm[gj];
        }

        const uint32_t* Tbase = g_hth + (size_t)b * LQ * KW;
        const float*    Abase = g_h   + (size_t)b * LQ * D;
        const uint32_t* Ap = Tbase + (size_t)(i0 + lrow) * KW + lc;
        const uint32_t* Bp = Tbase + (size_t)(j0 + lrow) * KW + lc;

        #pragma unroll
        for (int s = 0; s < 2; s++) {
            cpasync16(sA + s * PANELH * 4, Ap + s * 8);
            cpasync16(sB + s * PANELH * 4, Bp + s * 8);
            CP_COMMIT();
        }

        float acc[4][4][4] = {};
        for (int p = 0; p < nP; p++) {
            if (p + 1 < nP) CP_WAIT1(); else CP_WAIT0();
            __syncthreads();
            if (p + 2 < nP) {
                int st = (p + 2) % 3;
                cpasync16(sA + st * PANELH * 4, Ap + (p + 2) * 8);
                cpasync16(sB + st * PANELH * 4, Bp + (p + 2) * 8);
                CP_COMMIT();
            }
            uint32_t AbS = AsS + (p % 3) * PANELH * 4;
            uint32_t BbS = BsS + (p % 3) * PANELH * 4;
            uint32_t af[4][4], bf[4][2];
            #pragma unroll
            for (int mt = 0; mt < 4; mt++)
                ldsm4(af[mt], AbS + (wm * 64 + mt * 16) * KPH * 4 + laA);
            #pragma unroll
            for (int p2 = 0; p2 < 2; p2++) {
                int nb = wn * 32 + (2 * p2 + lbSel) * 8 + lbR;
                uint32_t tmp[4];
                ldsm4(tmp, BbS + (nb * KPH + lbKw) * 4);
                bf[2 * p2][0] = tmp[0]; bf[2 * p2][1] = tmp[1];
                bf[2 * p2 + 1][0] = tmp[2]; bf[2 * p2 + 1][1] = tmp[3];
            }
            #pragma unroll
            for (int mt = 0; mt < 4; mt++)
                #pragma unroll
                for (int nt = 0; nt < 4; nt++) mma16(acc[mt][nt], af[mt], bf[nt]);
        }
        __syncthreads();    // mainloop + all cp.async done; reuse dsm as byte staging

        unsigned char* Ms = (unsigned char*)dsm;            // [128][132]
        unsigned char* Ts = Ms + 128 * 132;                 // [128][132]

        #pragma unroll
        for (int mt = 0; mt < 4; mt++)
            #pragma unroll
            for (int h2 = 0; h2 < 2; h2++) {
                int ii = wm * 64 + mt * 16 + g + h2 * 8;
                int gi = i0 + ii;
                #pragma unroll
                for (int nt = 0; nt < 4; nt++) {
                    int jc = wn * 32 + nt * 8 + 2 * q;
                    #pragma unroll
                    for (int e = 0; e < 2; e++) {
                        int jj = jc + e, gj = j0 + jj;
                        float inv_nn = 1.f / (ni[ii] * nj[jj]);
                        float cosv = acc[mt][nt][h2 * 2 + e] * inv_nn;
                        if (fabsf(cosv - 0.2f) < 2e-3f) {
                            const float4* ra = (const float4*)(Abase + (size_t)gi * D);
                            const float4* rb = (const float4*)(Abase + (size_t)gj * D);
                            float dot = 0.f;
                            #pragma unroll 4
                            for (int k = 0; k < D / 4; k++) {
                                float4 x = ra[k], y = rb[k];
                                dot += x.x * y.x + x.y * y.y + x.z * y.z + x.w * y.w;
                            }
                            cosv = dot * inv_nn;
                        }
                        float inter = fmaxf(fminf(ei[ii], ej[jj]) - fmaxf(si[ii], sj[jj]), 0.f);
                        float uni   = li[ii] + lj[jj] - inter;
                        float iou   = inter / uni;
                        bool masked = (cosv <= 0.2f) || (iou > 0.2f && gi != gj);
                        unsigned char mb = masked ? 1 : 0;
                        Ms[ii * 132 + jj] = mb;
                        Ts[jj * 132 + ii] = mb;
                    }
                }
            }
        __syncthreads();

        {
            int row = tid >> 1, grp = tid & 1;
            const unsigned char* src = Ms + row * 132 + grp * 64;
            unsigned long long bits = 0ull;
            #pragma unroll 16
            for (int c = 0; c < 64; c++) bits |= (unsigned long long)src[c] << c;
            g_mbits[((size_t)b * LQ + i0 + row) * 16 + jt * 2 + grp] = bits;
            if (it != jt) {
                src = Ts + row * 132 + grp * 64;
                bits = 0ull;
                #pragma unroll 16
                for (int c = 0; c < 64; c++) bits |= (unsigned long long)src[c] << c;
                g_mbits[((size_t)b * LQ + j0 + row) * 16 + it * 2 + grp] = bits;
            }
        }
    }
}

// ---------------- K3: FA2 attention: fp16 QK^T + fp16 PV (ldmatrix.trans) ----------------
#define ATPH 36                    // half2 words per Q/K/V row (32 data + 4 pad)
__global__ __launch_bounds__(256, 2) void k_attn(float* __restrict__ out) {
    extern __shared__ float sm[];
    uint32_t* Qs = (uint32_t*)sm;          // 128*ATPH half2, persistent
    uint32_t* Ks = Qs + 128 * ATPH;        // 64*ATPH half2
    uint32_t* Vs = Ks + 64 * ATPH;         // 64*ATPH half2

    int i0 = blockIdx.x * 128, head = blockIdx.y, b = blockIdx.z;
    int tid = threadIdx.x, lane = tid & 31, wid = tid >> 5;
    int g = lane >> 2, q = lane & 3;
    const size_t baseh = (size_t)b * LQ * KW + head * (DH / 2);
    uint32_t QsS = (uint32_t)__cvta_generic_to_shared(Qs);
    uint32_t KsS = (uint32_t)__cvta_generic_to_shared(Ks);
    uint32_t VsS = (uint32_t)__cvta_generic_to_shared(Vs);

    // ldmatrix lane components
    int laA  = ((lane & 15) * ATPH + (lane >> 4) * 4) * 4;     // A (row-major 16x16)
    int lbR  = lane & 7;
    int lbSel = (lane >> 4);
    int lbKw = ((lane >> 3) & 1) * 4;
    // V trans tiles: tileIdx = lane>>3; row = kp*16 + (tile&1)*8 + (lane&7); colw = (tile>>1)*4
    int lvRow = ((lane >> 3) & 1) * 8 + (lane & 7);
    int lvCw  = (lane >> 4) * 4;

    #pragma unroll
    for (int s = 0; s < 4; s++) {
        int f = tid + s * 256;
        int r = f >> 3, w8 = (f & 7) << 2;
        cpasync16((uint32_t)__cvta_generic_to_shared(Qs + r * ATPH + w8),
                  &g_Qh[baseh + (size_t)(i0 + r) * KW + w8]);
    }
    CP_COMMIT();

    int lr = wid * 16;
    int gi0 = i0 + lr;
    float O[8][4] = {};
    float m0 = -1e30f, m1 = -1e30f, l0 = 0.f, l1 = 0.f;

    const unsigned long long* mb0 = g_mbits + ((size_t)b * LQ + gi0 + g) * 16;
    const unsigned long long* mb1 = g_mbits + ((size_t)b * LQ + gi0 + g + 8) * 16;

    for (int j = 0; j < 16; j++) {
        unsigned long long w0 = mb0[j], w1 = mb1[j];
        int any_un = ((w0 & w1) != 0xFFFFFFFFFFFFFFFFull);
        int blk_active = __syncthreads_or(any_un);
        if (!blk_active) continue;

        int j0 = j * 64;
        #pragma unroll
        for (int s = 0; s < 2; s++) {
            int f = tid + s * 256;
            int r = f >> 3, w8 = (f & 7) << 2;
            cpasync16((uint32_t)__cvta_generic_to_shared(Ks + r * ATPH + w8),
                      &g_Kh[baseh + (size_t)(j0 + r) * KW + w8]);
            cpasync16((uint32_t)__cvta_generic_to_shared(Vs + r * ATPH + w8),
                      &g_Vh[baseh + (size_t)(j0 + r) * KW + w8]);
        }
        CP_COMMIT();
        CP_WAIT0();
        __syncthreads();

        unsigned wact = __ballot_sync(0xffffffffu, any_un);
        if (!wact) continue;

        // S = (Q/8) K^T : fp16, 4 k16 panels over dh=64
        float S[8][4] = {};
        #pragma unroll
        for (int kp = 0; kp < 4; kp++) {
            uint32_t af[4];
            ldsm4(af, QsS + lr * ATPH * 4 + kp * 32 + laA);
            uint32_t bf[8][2];
            #pragma unroll
            for (int p2 = 0; p2 < 4; p2++) {
                int nb = (2 * p2 + lbSel) * 8 + lbR;
                uint32_t tmp[4];
                ldsm4(tmp, KsS + (nb * ATPH + kp * 8 + lbKw) * 4);
                bf[2 * p2][0] = tmp[0]; bf[2 * p2][1] = tmp[1];
                bf[2 * p2 + 1][0] = tmp[2]; bf[2 * p2 + 1][1] = tmp[3];
            }
            #pragma unroll
            for (int nt = 0; nt < 8; nt++) mma16(S[nt], af, bf[nt]);
        }

        #pragma unroll
        for (int nt = 0; nt < 8; nt++) {
            int c = nt * 8 + 2 * q;
            if ((w0 >> c) & 1)       S[nt][0] = -1e30f;
            if ((w0 >> (c + 1)) & 1) S[nt][1] = -1e30f;
            if ((w1 >> c) & 1)       S[nt][2] = -1e30f;
            if ((w1 >> (c + 1)) & 1) S[nt][3] = -1e30f;
        }

        float mx0 = -1e30f, mx1 = -1e30f;
        #pragma unroll
        for (int nt = 0; nt < 8; nt++) {
            mx0 = fmaxf(mx0, fmaxf(S[nt][0], S[nt][1]));
            mx1 = fmaxf(mx1, fmaxf(S[nt][2], S[nt][3]));
        }
        #pragma unroll
        for (int o = 1; o < 4; o <<= 1) {
            mx0 = fmaxf(mx0, __shfl_xor_sync(0xffffffffu, mx0, o));
            mx1 = fmaxf(mx1, __shfl_xor_sync(0xffffffffu, mx1, o));
        }
        float mn0 = fmaxf(m0, mx0), mn1 = fmaxf(m1, mx1);

        // exp; pack P as fp16 A-fragments in registers
        uint32_t Ph[8][2];
        float s0 = 0.f, s1 = 0.f;
        #pragma unroll
        for (int nt = 0; nt < 8; nt++) {
            float p00 = __expf(S[nt][0] - mn0), p01 = __expf(S[nt][1] - mn0);
            float p10 = __expf(S[nt][2] - mn1), p11 = __expf(S[nt][3] - mn1);
            s0 += p00 + p01; s1 += p10 + p11;
            Ph[nt][0] = pack_h2(p00, p01);
            Ph[nt][1] = pack_h2(p10, p11);
        }
        #pragma unroll
        for (int o = 1; o < 4; o <<= 1) {
            s0 += __shfl_xor_sync(0xffffffffu, s0, o);
            s1 += __shfl_xor_sync(0xffffffffu, s1, o);
        }
        float sc0 = __expf(m0 - mn0), sc1 = __expf(m1 - mn1);
        l0 = l0 * sc0 + s0; l1 = l1 * sc1 + s1;
        m0 = mn0; m1 = mn1;

        #pragma unroll
        for (int nt = 0; nt < 8; nt++) {
            O[nt][0] *= sc0; O[nt][1] *= sc0;
            O[nt][2] *= sc1; O[nt][3] *= sc1;
        }

        // O += P V : fp16, 4 k16 panels over 64 keys; V B-fragments via ldmatrix.trans
        #pragma unroll
        for (int kp = 0; kp < 4; kp++) {
            uint32_t af[4] = {Ph[2 * kp][0], Ph[2 * kp][1], Ph[2 * kp + 1][0], Ph[2 * kp + 1][1]};
            #pragma unroll
            for (int p2 = 0; p2 < 4; p2++) {
                uint32_t tmp[4];
                // rows: key = kp*16 + lvRow; col words: p2*8 + lvCw
                ldsm4t(tmp, VsS + ((kp * 16 + lvRow) * ATPH + p2 * 8 + lvCw) * 4);
                uint32_t bf0[2] = {tmp[0], tmp[1]};
                uint32_t bf1[2] = {tmp[2], tmp[3]};
                mma16(O[2 * p2], af, bf0);
                mma16(O[2 * p2 + 1], af, bf1);
            }
        }
    }

    float inv0 = 1.f / l0, inv1 = 1.f / l1;
    int r0 = gi0 + g, r1 = gi0 + g + 8;
    #pragma unroll
    for (int nt = 0; nt < 8; nt++) {
        int col = head * DH + nt * 8 + 2 * q;
        float2 h0 = *(const float2*)&g_h[((size_t)b * LQ + r0) * D + col];
        float2 h1 = *(const float2*)&g_h[((size_t)b * LQ + r1) * D + col];
        float2 o0, o1;
        o0.x = O[nt][0] * inv0 + h0.x; o0.y = O[nt][1] * inv0 + h0.y;
        o1.x = O[nt][2] * inv1 + h1.x; o1.y = O[nt][3] * inv1 + h1.y;
        *(float2*)&out[((size_t)r0 * BZ + b) * D + col] = o0;
        *(float2*)&out[((size_t)r1 * BZ + b) * D + col] = o1;
    }
}

// ---------------- host ----------------
extern "C" void kernel_launch(void* const* d_in, const int* in_sizes, int n_in,
                              void* d_out, int out_size) {
    const float* query = (const float*)d_in[0];
    const float* seg   = (const float*)d_in[1];
    const float* Wq    = (const float*)d_in[2];
    const float* bq    = (const float*)d_in[3];
    const float* Wk    = (const float*)d_in[4];
    const float* bk    = (const float*)d_in[5];
    const float* Wv    = (const float*)d_in[6];
    const float* bv    = (const float*)d_in[7];
    float* out = (float*)d_out;

    k_prep<<<BZ * LQ + 3 * 65536 / 128, 128>>>(query, Wq, Wk, Wv);

    int smem_g = 6 * PANELH * (int)sizeof(uint32_t);   // 36864 B
    cudaFuncSetAttribute(k_gemm_mask, cudaFuncAttributeMaxDynamicSharedMemorySize, smem_g);
    k_gemm_mask<<<GEMM_BLOCKS + MASK_BLOCKS * BZ, 256, smem_g>>>(seg, bq, bk, bv);

    int smem_a = (128 * ATPH + 64 * ATPH + 64 * ATPH) * (int)sizeof(uint32_t);  // 36864 B
    cudaFuncSetAttribute(k_attn, cudaFuncAttributeMaxDynamicSharedMemorySize, smem_a);
    dim3 ga(LQ / 128, NH, BZ);            // (8, 8, 8)
    k_attn<<<ga, 256, smem_a>>>(out);
}